// round 1
// baseline (speedup 1.0000x reference)
#include <cuda_runtime.h>
#include <cuda_bf16.h>
#include <math.h>

// ---------------------------------------------------------------------------
// Problem constants
// ---------------------------------------------------------------------------
#define BATCH   2
#define SEQ     2048
#define DMODEL  1024
#define NHEAD   16
#define HDIM    64
#define MROWS   (BATCH * SEQ)      // 4096

// ---------------------------------------------------------------------------
// Scratch (static device globals; allocation inside kernel_launch is banned)
// ---------------------------------------------------------------------------
__device__ float g_Q[MROWS * DMODEL];
__device__ float g_K[MROWS * DMODEL];
__device__ float g_V[MROWS * DMODEL];
__device__ float g_A[MROWS * DMODEL];   // attention output (pre-Wo)

// ---------------------------------------------------------------------------
// SGEMM: C[M,N] = A[M,K] * B[K,N], all row-major, fp32.
// 128x128 tile, BK=8, 8x8 per thread, 256 threads. M%128==0, N%128==0, K%8==0.
// ---------------------------------------------------------------------------
#define GBM 128
#define GBN 128
#define GBK 8
#define GTM 8
#define GTN 8

__global__ __launch_bounds__(256, 2)
void sgemm128(const float* __restrict__ A, const float* __restrict__ Bw,
              float* __restrict__ C, int M, int N, int K)
{
    __shared__ float As[GBK][GBM];
    __shared__ float Bs[GBK][GBN];

    const int tid  = threadIdx.x;
    const int cRow = blockIdx.y;
    const int cCol = blockIdx.x;

    const int threadRow = tid / (GBN / GTN);   // 0..15
    const int threadCol = tid % (GBN / GTN);   // 0..15

    const float* Aptr = A + (size_t)cRow * GBM * K;
    const float* Bptr = Bw + (size_t)cCol * GBN;
    float*       Cptr = C + (size_t)cRow * GBM * N + (size_t)cCol * GBN;

    const int innerRowA = tid / (GBK / 4);          // 0..127
    const int innerColA = (tid % (GBK / 4)) * 4;    // 0 or 4
    const int innerRowB = tid / (GBN / 4);          // 0..7
    const int innerColB = (tid % (GBN / 4)) * 4;    // 0..124

    float acc[GTM][GTN] = {};
    float regM[GTM], regN[GTN];

    for (int k0 = 0; k0 < K; k0 += GBK) {
        float4 a = *(const float4*)(Aptr + (size_t)innerRowA * K + k0 + innerColA);
        As[innerColA + 0][innerRowA] = a.x;
        As[innerColA + 1][innerRowA] = a.y;
        As[innerColA + 2][innerRowA] = a.z;
        As[innerColA + 3][innerRowA] = a.w;
        *(float4*)(&Bs[innerRowB][innerColB]) =
            *(const float4*)(Bptr + (size_t)(k0 + innerRowB) * N + innerColB);
        __syncthreads();

        #pragma unroll
        for (int k = 0; k < GBK; ++k) {
            #pragma unroll
            for (int i = 0; i < GTM; ++i) regM[i] = As[k][threadRow * GTM + i];
            #pragma unroll
            for (int j = 0; j < GTN; ++j) regN[j] = Bs[k][threadCol * GTN + j];
            #pragma unroll
            for (int i = 0; i < GTM; ++i)
                #pragma unroll
                for (int j = 0; j < GTN; ++j)
                    acc[i][j] += regM[i] * regN[j];
        }
        __syncthreads();
    }

    #pragma unroll
    for (int i = 0; i < GTM; ++i) {
        #pragma unroll
        for (int j = 0; j < GTN; j += 4) {
            float4 v = make_float4(acc[i][j], acc[i][j+1], acc[i][j+2], acc[i][j+3]);
            *(float4*)(Cptr + (size_t)(threadRow * GTM + i) * N + threadCol * GTN + j) = v;
        }
    }
}

// ---------------------------------------------------------------------------
// Fused flash attention, fp32.
// One thread per query row (q, o accumulators in registers).
// Block = 128 threads = 128 query rows of one (b, h). K/V tiles (64 keys) in smem.
// Online softmax: rescale only when running max changes.
// ---------------------------------------------------------------------------
#define BQ   128
#define BKV  64

__global__ __launch_bounds__(128)
void attn_kernel(const float* __restrict__ Q, const float* __restrict__ K,
                 const float* __restrict__ V, const int* __restrict__ mask,
                 const int* __restrict__ causal_p, float* __restrict__ O)
{
    __shared__ float4 Ks4[BKV][HDIM / 4];
    __shared__ float4 Vs4[BKV][HDIM / 4];
    __shared__ int    Ms[BKV];

    const int b   = blockIdx.z;
    const int h   = blockIdx.y;
    const int qt  = blockIdx.x;
    const int tid = threadIdx.x;
    const int qrow = qt * BQ + tid;
    const int causal = *causal_p;

    // load q into registers (float4 x16)
    float4 q4[HDIM / 4];
    {
        const float4* qptr = (const float4*)(Q + ((size_t)(b * SEQ + qrow)) * DMODEL + h * HDIM);
        #pragma unroll
        for (int d = 0; d < HDIM / 4; ++d) q4[d] = qptr[d];
    }

    float4 o4[HDIM / 4];
    #pragma unroll
    for (int d = 0; d < HDIM / 4; ++d) o4[d] = make_float4(0.f, 0.f, 0.f, 0.f);
    float m = -INFINITY, l = 0.f;

    int kend = causal ? (qt * BQ + BQ) : SEQ;       // exclusive bound on keys this block needs
    if (kend > SEQ) kend = SEQ;
    const int ntiles = (kend + BKV - 1) / BKV;

    for (int t = 0; t < ntiles; ++t) {
        const int kbase = t * BKV;
        // cooperative load: 64 rows x 16 float4 per tile, 128 threads -> 8 float4 each per tensor
        {
            const float* kg = K + ((size_t)(b * SEQ + kbase)) * DMODEL + h * HDIM;
            const float* vg = V + ((size_t)(b * SEQ + kbase)) * DMODEL + h * HDIM;
            #pragma unroll
            for (int i = tid; i < BKV * (HDIM / 4); i += 128) {
                int r = i / (HDIM / 4);
                int c = i % (HDIM / 4);
                Ks4[r][c] = *(const float4*)(kg + (size_t)r * DMODEL + c * 4);
                Vs4[r][c] = *(const float4*)(vg + (size_t)r * DMODEL + c * 4);
            }
            if (tid < BKV) Ms[tid] = mask[b * SEQ + kbase + tid];
        }
        __syncthreads();

        int klim = BKV;
        if (causal) {
            int lim = qrow - kbase + 1;
            klim = lim < BKV ? lim : BKV;
        }
        for (int kk = 0; kk < klim; ++kk) {
            if (!Ms[kk]) continue;
            float s = 0.f;
            #pragma unroll
            for (int d = 0; d < HDIM / 4; ++d) {
                float4 kv = Ks4[kk][d];
                s += q4[d].x * kv.x + q4[d].y * kv.y + q4[d].z * kv.z + q4[d].w * kv.w;
            }
            s *= 0.125f;   // 1/sqrt(64)
            if (s > m) {
                float scale = __expf(m - s);   // exp(-inf) = 0 handles first key
                l *= scale;
                #pragma unroll
                for (int d = 0; d < HDIM / 4; ++d) {
                    o4[d].x *= scale; o4[d].y *= scale;
                    o4[d].z *= scale; o4[d].w *= scale;
                }
                m = s;
            }
            float p = __expf(s - m);
            l += p;
            #pragma unroll
            for (int d = 0; d < HDIM / 4; ++d) {
                float4 vv = Vs4[kk][d];
                o4[d].x += p * vv.x; o4[d].y += p * vv.y;
                o4[d].z += p * vv.z; o4[d].w += p * vv.w;
            }
        }
        __syncthreads();
    }

    const float inv = 1.f / l;
    float4* optr = (float4*)(O + ((size_t)(b * SEQ + qrow)) * DMODEL + h * HDIM);
    #pragma unroll
    for (int d = 0; d < HDIM / 4; ++d) {
        float4 v = o4[d];
        v.x *= inv; v.y *= inv; v.z *= inv; v.w *= inv;
        optr[d] = v;
    }
}

// ---------------------------------------------------------------------------
// Launch
// ---------------------------------------------------------------------------
extern "C" void kernel_launch(void* const* d_in, const int* in_sizes, int n_in,
                              void* d_out, int out_size)
{
    const float* x      = (const float*)d_in[0];
    const int*   mask   = (const int*)  d_in[1];
    const int*   causal = (const int*)  d_in[2];
    const float* Wq     = (const float*)d_in[3];
    const float* Wk     = (const float*)d_in[4];
    const float* Wv     = (const float*)d_in[5];
    const float* Wo     = (const float*)d_in[6];
    float*       out    = (float*)d_out;

    float *qp, *kp, *vp, *ap;
    cudaGetSymbolAddress((void**)&qp, g_Q);
    cudaGetSymbolAddress((void**)&kp, g_K);
    cudaGetSymbolAddress((void**)&vp, g_V);
    cudaGetSymbolAddress((void**)&ap, g_A);

    dim3 ggrid(DMODEL / GBN, MROWS / GBM);   // (8, 32)
    dim3 gblk(256);

    sgemm128<<<ggrid, gblk>>>(x, Wq, qp, MROWS, DMODEL, DMODEL);
    sgemm128<<<ggrid, gblk>>>(x, Wk, kp, MROWS, DMODEL, DMODEL);
    sgemm128<<<ggrid, gblk>>>(x, Wv, vp, MROWS, DMODEL, DMODEL);

    dim3 agrid(SEQ / BQ, NHEAD, BATCH);      // (16, 16, 2)
    attn_kernel<<<agrid, 128>>>(qp, kp, vp, mask, causal, ap);

    sgemm128<<<ggrid, gblk>>>(ap, Wo, out, MROWS, DMODEL, DMODEL);
}

// round 4
// speedup vs baseline: 1.1255x; 1.1255x over previous
#include <cuda_runtime.h>
#include <cuda_bf16.h>
#include <math.h>
#include <stdint.h>

// ---------------------------------------------------------------------------
// Problem constants
// ---------------------------------------------------------------------------
#define BATCH   2
#define SEQ     2048
#define DMODEL  1024
#define NHEAD   16
#define HDIM    64
#define MROWS   (BATCH * SEQ)      // 4096

// ---------------------------------------------------------------------------
// Scratch (static device globals; allocation inside kernel_launch is banned)
// ---------------------------------------------------------------------------
__device__ float g_Q[MROWS * DMODEL];
__device__ float g_K[MROWS * DMODEL];
__device__ float g_V[MROWS * DMODEL];
__device__ float g_A[MROWS * DMODEL];   // attention output (pre-Wo)

// ---------------------------------------------------------------------------
// 3xTF32 tensor-core GEMM: C[M,N] = A[M,K] * B[K,N], row-major fp32 in/out.
// Each operand split big/small (tf32); C += As*Bb + Ab*Bs + Ab*Bb gives
// near-fp32 precision at 3x tensor-op cost.
// 128x128x32 tile, 256 threads (8 warps as 2x4), warp tile 64x32.
// ---------------------------------------------------------------------------
#define BM 128
#define BN 128
#define BK 32
#define ASTR 36            // 32 + 4 pad  -> conflict-free
#define BSTR 136           // 128 + 8 pad -> conflict-free
#define ABUF (BM * ASTR)
#define BBUF (BK * BSTR)
#define GEMM_SMEM_BYTES ((2 * ABUF + 2 * BBUF) * 4)   // 71680

__device__ __forceinline__ void cp_async16(void* smem_dst, const void* gsrc) {
    uint32_t d = (uint32_t)__cvta_generic_to_shared(smem_dst);
    asm volatile("cp.async.cg.shared.global [%0], [%1], 16;\n" :: "r"(d), "l"(gsrc));
}

// split fp32 into tf32 big + tf32 small (residual)
__device__ __forceinline__ void tf32_split(float a, uint32_t& big, uint32_t& small) {
    asm("cvt.rna.tf32.f32 %0, %1;\n" : "=r"(big) : "f"(a));
    float r = a - __uint_as_float(big);
    asm("cvt.rna.tf32.f32 %0, %1;\n" : "=r"(small) : "f"(r));
}

#define MMA_TF32(ACC, Afrag, B0, B1)                                        \
    asm volatile(                                                           \
        "mma.sync.aligned.m16n8k8.row.col.f32.tf32.tf32.f32 "               \
        "{%0,%1,%2,%3}, {%4,%5,%6,%7}, {%8,%9}, {%0,%1,%2,%3};\n"           \
        : "+f"(ACC[0]), "+f"(ACC[1]), "+f"(ACC[2]), "+f"(ACC[3])            \
        : "r"(Afrag[0]), "r"(Afrag[1]), "r"(Afrag[2]), "r"(Afrag[3]),       \
          "r"(B0), "r"(B1))

__global__ __launch_bounds__(256)
void tf32gemm(const float* __restrict__ A, const float* __restrict__ Bw,
              float* __restrict__ C, int M, int N, int K)
{
    extern __shared__ float sm[];
    float* As = sm;                 // [2][BM][ASTR]
    float* Bs = sm + 2 * ABUF;      // [2][BK][BSTR]

    const int tid  = threadIdx.x;
    const int lane = tid & 31;
    const int wid  = tid >> 5;
    const int g    = lane >> 2;     // 0..7
    const int tg   = lane & 3;      // 0..3
    const int warp_m = wid >> 2;    // 0..1
    const int warp_n = wid & 3;     // 0..3

    const int bM = blockIdx.y * BM;
    const int bN = blockIdx.x * BN;

    const float* Ag = A + (size_t)bM * K;
    const float* Bg = Bw + bN;

    float acc[4][4][4];
    #pragma unroll
    for (int i = 0; i < 4; ++i)
        #pragma unroll
        for (int j = 0; j < 4; ++j)
            #pragma unroll
            for (int c = 0; c < 4; ++c) acc[i][j][c] = 0.f;

    const int NK = K / BK;

    // ---- prologue: stage 0 ----
    {
        #pragma unroll
        for (int j = 0; j < 4; ++j) {
            int idx = tid + j * 256;
            int r = idx >> 3, q = idx & 7;
            cp_async16(&As[r * ASTR + q * 4], Ag + (size_t)r * K + q * 4);
        }
        #pragma unroll
        for (int j = 0; j < 4; ++j) {
            int idx = tid + j * 256;
            int r = idx >> 5, q = idx & 31;
            cp_async16(&Bs[r * BSTR + q * 4], Bg + (size_t)r * N + q * 4);
        }
        asm volatile("cp.async.commit_group;\n");
    }

    int buf = 0;
    for (int kt = 0; kt < NK; ++kt) {
        asm volatile("cp.async.wait_group 0;\n");
        __syncthreads();

        if (kt + 1 < NK) {
            const int k0 = (kt + 1) * BK;
            const int ob = buf ^ 1;
            #pragma unroll
            for (int j = 0; j < 4; ++j) {
                int idx = tid + j * 256;
                int r = idx >> 3, q = idx & 7;
                cp_async16(&As[ob * ABUF + r * ASTR + q * 4],
                           Ag + (size_t)r * K + k0 + q * 4);
            }
            #pragma unroll
            for (int j = 0; j < 4; ++j) {
                int idx = tid + j * 256;
                int r = idx >> 5, q = idx & 31;
                cp_async16(&Bs[ob * BBUF + r * BSTR + q * 4],
                           Bg + (size_t)(k0 + r) * N + q * 4);
            }
            asm volatile("cp.async.commit_group;\n");
        }

        // ---- compute on buf ----
        const float* Ab = &As[buf * ABUF + (warp_m * 64) * ASTR];
        const float* Bb = &Bs[buf * BBUF + warp_n * 32];
        #pragma unroll
        for (int ks = 0; ks < 4; ++ks) {
            const int k = ks * 8;
            uint32_t abig[4][4], asml[4][4], bbig[4][2], bsml[4][2];
            #pragma unroll
            for (int mt = 0; mt < 4; ++mt) {
                const float* p = Ab + (mt * 16 + g) * ASTR + k + tg;
                tf32_split(p[0],            abig[mt][0], asml[mt][0]);
                tf32_split(p[8 * ASTR],     abig[mt][1], asml[mt][1]);
                tf32_split(p[4],            abig[mt][2], asml[mt][2]);
                tf32_split(p[8 * ASTR + 4], abig[mt][3], asml[mt][3]);
            }
            #pragma unroll
            for (int nt = 0; nt < 4; ++nt) {
                const float* p = Bb + (k + tg) * BSTR + nt * 8 + g;
                tf32_split(p[0],        bbig[nt][0], bsml[nt][0]);
                tf32_split(p[4 * BSTR], bbig[nt][1], bsml[nt][1]);
            }
            #pragma unroll
            for (int mt = 0; mt < 4; ++mt)
                #pragma unroll
                for (int nt = 0; nt < 4; ++nt) {
                    MMA_TF32(acc[mt][nt], asml[mt], bbig[nt][0], bbig[nt][1]);
                    MMA_TF32(acc[mt][nt], abig[mt], bsml[nt][0], bsml[nt][1]);
                    MMA_TF32(acc[mt][nt], abig[mt], bbig[nt][0], bbig[nt][1]);
                }
        }
        __syncthreads();
        buf ^= 1;
    }

    // ---- epilogue ----
    float* Cb = C + (size_t)(bM + warp_m * 64) * N + bN + warp_n * 32;
    #pragma unroll
    for (int mt = 0; mt < 4; ++mt) {
        #pragma unroll
        for (int nt = 0; nt < 4; ++nt) {
            float* p0 = Cb + (size_t)(mt * 16 + g) * N + nt * 8 + 2 * tg;
            float* p1 = Cb + (size_t)(mt * 16 + g + 8) * N + nt * 8 + 2 * tg;
            *(float2*)p0 = make_float2(acc[mt][nt][0], acc[mt][nt][1]);
            *(float2*)p1 = make_float2(acc[mt][nt][2], acc[mt][nt][3]);
        }
    }
}

// ---------------------------------------------------------------------------
// Fused flash attention, fp32 (unchanged — known correct).
// ---------------------------------------------------------------------------
#define BQ   128
#define BKV  64

__global__ __launch_bounds__(128)
void attn_kernel(const float* __restrict__ Q, const float* __restrict__ K,
                 const float* __restrict__ V, const int* __restrict__ mask,
                 const int* __restrict__ causal_p, float* __restrict__ O)
{
    __shared__ float4 Ks4[BKV][HDIM / 4];
    __shared__ float4 Vs4[BKV][HDIM / 4];
    __shared__ int    Ms[BKV];

    const int b   = blockIdx.z;
    const int h   = blockIdx.y;
    const int qt  = blockIdx.x;
    const int tid = threadIdx.x;
    const int qrow = qt * BQ + tid;
    const int causal = *causal_p;

    float4 q4[HDIM / 4];
    {
        const float4* qptr = (const float4*)(Q + ((size_t)(b * SEQ + qrow)) * DMODEL + h * HDIM);
        #pragma unroll
        for (int d = 0; d < HDIM / 4; ++d) q4[d] = qptr[d];
    }

    float4 o4[HDIM / 4];
    #pragma unroll
    for (int d = 0; d < HDIM / 4; ++d) o4[d] = make_float4(0.f, 0.f, 0.f, 0.f);
    float m = -INFINITY, l = 0.f;

    int kend = causal ? (qt * BQ + BQ) : SEQ;
    if (kend > SEQ) kend = SEQ;
    const int ntiles = (kend + BKV - 1) / BKV;

    for (int t = 0; t < ntiles; ++t) {
        const int kbase = t * BKV;
        {
            const float* kg = K + ((size_t)(b * SEQ + kbase)) * DMODEL + h * HDIM;
            const float* vg = V + ((size_t)(b * SEQ + kbase)) * DMODEL + h * HDIM;
            #pragma unroll
            for (int i = tid; i < BKV * (HDIM / 4); i += 128) {
                int r = i / (HDIM / 4);
                int c = i % (HDIM / 4);
                Ks4[r][c] = *(const float4*)(kg + (size_t)r * DMODEL + c * 4);
                Vs4[r][c] = *(const float4*)(vg + (size_t)r * DMODEL + c * 4);
            }
            if (tid < BKV) Ms[tid] = mask[b * SEQ + kbase + tid];
        }
        __syncthreads();

        int klim = BKV;
        if (causal) {
            int lim = qrow - kbase + 1;
            klim = lim < BKV ? lim : BKV;
        }
        for (int kk = 0; kk < klim; ++kk) {
            if (!Ms[kk]) continue;
            float s = 0.f;
            #pragma unroll
            for (int d = 0; d < HDIM / 4; ++d) {
                float4 kv = Ks4[kk][d];
                s += q4[d].x * kv.x + q4[d].y * kv.y + q4[d].z * kv.z + q4[d].w * kv.w;
            }
            s *= 0.125f;
            if (s > m) {
                float scale = __expf(m - s);
                l *= scale;
                #pragma unroll
                for (int d = 0; d < HDIM / 4; ++d) {
                    o4[d].x *= scale; o4[d].y *= scale;
                    o4[d].z *= scale; o4[d].w *= scale;
                }
                m = s;
            }
            float p = __expf(s - m);
            l += p;
            #pragma unroll
            for (int d = 0; d < HDIM / 4; ++d) {
                float4 vv = Vs4[kk][d];
                o4[d].x += p * vv.x; o4[d].y += p * vv.y;
                o4[d].z += p * vv.z; o4[d].w += p * vv.w;
            }
        }
        __syncthreads();
    }

    const float inv = 1.f / l;
    float4* optr = (float4*)(O + ((size_t)(b * SEQ + qrow)) * DMODEL + h * HDIM);
    #pragma unroll
    for (int d = 0; d < HDIM / 4; ++d) {
        float4 v = o4[d];
        v.x *= inv; v.y *= inv; v.z *= inv; v.w *= inv;
        optr[d] = v;
    }
}

// ---------------------------------------------------------------------------
// Launch
// ---------------------------------------------------------------------------
extern "C" void kernel_launch(void* const* d_in, const int* in_sizes, int n_in,
                              void* d_out, int out_size)
{
    const float* x      = (const float*)d_in[0];
    const int*   mask   = (const int*)  d_in[1];
    const int*   causal = (const int*)  d_in[2];
    const float* Wq     = (const float*)d_in[3];
    const float* Wk     = (const float*)d_in[4];
    const float* Wv     = (const float*)d_in[5];
    const float* Wo     = (const float*)d_in[6];
    float*       out    = (float*)d_out;

    float *qp, *kp, *vp, *ap;
    cudaGetSymbolAddress((void**)&qp, g_Q);
    cudaGetSymbolAddress((void**)&kp, g_K);
    cudaGetSymbolAddress((void**)&vp, g_V);
    cudaGetSymbolAddress((void**)&ap, g_A);

    static bool attr_done = false;
    if (!attr_done) {
        cudaFuncSetAttribute(tf32gemm, cudaFuncAttributeMaxDynamicSharedMemorySize,
                             GEMM_SMEM_BYTES);
        attr_done = true;
    }

    dim3 ggrid(DMODEL / BN, MROWS / BM);   // (8, 32)
    dim3 gblk(256);

    tf32gemm<<<ggrid, gblk, GEMM_SMEM_BYTES>>>(x, Wq, qp, MROWS, DMODEL, DMODEL);
    tf32gemm<<<ggrid, gblk, GEMM_SMEM_BYTES>>>(x, Wk, kp, MROWS, DMODEL, DMODEL);
    tf32gemm<<<ggrid, gblk, GEMM_SMEM_BYTES>>>(x, Wv, vp, MROWS, DMODEL, DMODEL);

    dim3 agrid(SEQ / BQ, NHEAD, BATCH);    // (16, 16, 2)
    attn_kernel<<<agrid, 128>>>(qp, kp, vp, mask, causal, ap);

    tf32gemm<<<ggrid, gblk, GEMM_SMEM_BYTES>>>(ap, Wo, out, MROWS, DMODEL, DMODEL);
}

// round 8
// speedup vs baseline: 1.4600x; 1.2972x over previous
#include <cuda_runtime.h>
#include <cuda_bf16.h>
#include <math.h>
#include <stdint.h>

// ---------------------------------------------------------------------------
// Problem constants
// ---------------------------------------------------------------------------
#define BATCH   2
#define SEQ     2048
#define DMODEL  1024
#define NHEAD   16
#define HDIM    64
#define MROWS   (BATCH * SEQ)      // 4096

// ---------------------------------------------------------------------------
// Scratch
// ---------------------------------------------------------------------------
__device__ float g_Q[MROWS * DMODEL];
__device__ float g_K[MROWS * DMODEL];
__device__ float g_V[MROWS * DMODEL];
__device__ float g_A[MROWS * DMODEL];

// ---------------------------------------------------------------------------
// Common helpers
// ---------------------------------------------------------------------------
__device__ __forceinline__ void cp_async16(void* smem_dst, const void* gsrc) {
    uint32_t d = (uint32_t)__cvta_generic_to_shared(smem_dst);
    asm volatile("cp.async.cg.shared.global [%0], [%1], 16;\n" :: "r"(d), "l"(gsrc));
}

__device__ __forceinline__ void tf32_split(float a, uint32_t& big, uint32_t& small) {
    asm("cvt.rna.tf32.f32 %0, %1;\n" : "=r"(big) : "f"(a));
    float r = a - __uint_as_float(big);
    asm("cvt.rna.tf32.f32 %0, %1;\n" : "=r"(small) : "f"(r));
}

#define MMA_TF32(ACC, Afrag, B0, B1)                                        \
    asm volatile(                                                           \
        "mma.sync.aligned.m16n8k8.row.col.f32.tf32.tf32.f32 "               \
        "{%0,%1,%2,%3}, {%4,%5,%6,%7}, {%8,%9}, {%0,%1,%2,%3};\n"           \
        : "+f"(ACC[0]), "+f"(ACC[1]), "+f"(ACC[2]), "+f"(ACC[3])            \
        : "r"(Afrag[0]), "r"(Afrag[1]), "r"(Afrag[2]), "r"(Afrag[3]),       \
          "r"(B0), "r"(B1))

// ---------------------------------------------------------------------------
// 3xTF32 GEMM (unchanged — passing, rel_err 2.5e-5)
// ---------------------------------------------------------------------------
#define BM 128
#define BN 128
#define BK 32
#define ASTR 36
#define BSTR 136
#define ABUF (BM * ASTR)
#define BBUF (BK * BSTR)
#define GEMM_SMEM_BYTES ((2 * ABUF + 2 * BBUF) * 4)

__global__ __launch_bounds__(256)
void tf32gemm(const float* __restrict__ A, const float* __restrict__ Bw,
              float* __restrict__ C, int M, int N, int K)
{
    extern __shared__ float sm[];
    float* As = sm;
    float* Bs = sm + 2 * ABUF;

    const int tid  = threadIdx.x;
    const int lane = tid & 31;
    const int wid  = tid >> 5;
    const int g    = lane >> 2;
    const int tg   = lane & 3;
    const int warp_m = wid >> 2;
    const int warp_n = wid & 3;

    const int bM = blockIdx.y * BM;
    const int bN = blockIdx.x * BN;

    const float* Ag = A + (size_t)bM * K;
    const float* Bg = Bw + bN;

    float acc[4][4][4];
    #pragma unroll
    for (int i = 0; i < 4; ++i)
        #pragma unroll
        for (int j = 0; j < 4; ++j)
            #pragma unroll
            for (int c = 0; c < 4; ++c) acc[i][j][c] = 0.f;

    const int NK = K / BK;

    {
        #pragma unroll
        for (int j = 0; j < 4; ++j) {
            int idx = tid + j * 256;
            int r = idx >> 3, q = idx & 7;
            cp_async16(&As[r * ASTR + q * 4], Ag + (size_t)r * K + q * 4);
        }
        #pragma unroll
        for (int j = 0; j < 4; ++j) {
            int idx = tid + j * 256;
            int r = idx >> 5, q = idx & 31;
            cp_async16(&Bs[r * BSTR + q * 4], Bg + (size_t)r * N + q * 4);
        }
        asm volatile("cp.async.commit_group;\n");
    }

    int buf = 0;
    for (int kt = 0; kt < NK; ++kt) {
        asm volatile("cp.async.wait_group 0;\n");
        __syncthreads();

        if (kt + 1 < NK) {
            const int k0 = (kt + 1) * BK;
            const int ob = buf ^ 1;
            #pragma unroll
            for (int j = 0; j < 4; ++j) {
                int idx = tid + j * 256;
                int r = idx >> 3, q = idx & 7;
                cp_async16(&As[ob * ABUF + r * ASTR + q * 4],
                           Ag + (size_t)r * K + k0 + q * 4);
            }
            #pragma unroll
            for (int j = 0; j < 4; ++j) {
                int idx = tid + j * 256;
                int r = idx >> 5, q = idx & 31;
                cp_async16(&Bs[ob * BBUF + r * BSTR + q * 4],
                           Bg + (size_t)(k0 + r) * N + q * 4);
            }
            asm volatile("cp.async.commit_group;\n");
        }

        const float* Ab = &As[buf * ABUF + (warp_m * 64) * ASTR];
        const float* Bb = &Bs[buf * BBUF + warp_n * 32];
        #pragma unroll
        for (int ks = 0; ks < 4; ++ks) {
            const int k = ks * 8;
            uint32_t abig[4][4], asml[4][4], bbig[4][2], bsml[4][2];
            #pragma unroll
            for (int mt = 0; mt < 4; ++mt) {
                const float* p = Ab + (mt * 16 + g) * ASTR + k + tg;
                tf32_split(p[0],            abig[mt][0], asml[mt][0]);
                tf32_split(p[8 * ASTR],     abig[mt][1], asml[mt][1]);
                tf32_split(p[4],            abig[mt][2], asml[mt][2]);
                tf32_split(p[8 * ASTR + 4], abig[mt][3], asml[mt][3]);
            }
            #pragma unroll
            for (int nt = 0; nt < 4; ++nt) {
                const float* p = Bb + (k + tg) * BSTR + nt * 8 + g;
                tf32_split(p[0],        bbig[nt][0], bsml[nt][0]);
                tf32_split(p[4 * BSTR], bbig[nt][1], bsml[nt][1]);
            }
            #pragma unroll
            for (int mt = 0; mt < 4; ++mt)
                #pragma unroll
                for (int nt = 0; nt < 4; ++nt) {
                    MMA_TF32(acc[mt][nt], asml[mt], bbig[nt][0], bbig[nt][1]);
                    MMA_TF32(acc[mt][nt], abig[mt], bsml[nt][0], bsml[nt][1]);
                    MMA_TF32(acc[mt][nt], abig[mt], bbig[nt][0], bbig[nt][1]);
                }
        }
        __syncthreads();
        buf ^= 1;
    }

    float* Cb = C + (size_t)(bM + warp_m * 64) * N + bN + warp_n * 32;
    #pragma unroll
    for (int mt = 0; mt < 4; ++mt) {
        #pragma unroll
        for (int nt = 0; nt < 4; ++nt) {
            float* p0 = Cb + (size_t)(mt * 16 + g) * N + nt * 8 + 2 * tg;
            float* p1 = Cb + (size_t)(mt * 16 + g + 8) * N + nt * 8 + 2 * tg;
            *(float2*)p0 = make_float2(acc[mt][nt][0], acc[mt][nt][1]);
            *(float2*)p1 = make_float2(acc[mt][nt][2], acc[mt][nt][3]);
        }
    }
}

// ---------------------------------------------------------------------------
// Tensor-core flash attention (3xTF32, m16n8k8).
// Block: 128 queries of one (b,h); 8 warps x 16 query rows each. (256 threads)
// KV tiles of 64 keys; K/V split big/small in smem; online softmax in regs.
// ---------------------------------------------------------------------------
#define AQT  128
#define AKT  64
#define QSTR 68            // (4g+tg)%32 conflict-free for A-frag loads
#define KSTR 68
#define VSTR 72            // (8tg+g)%32 conflict-free for B-frag loads
#define PSTR 68

#define SM_Q    0
#define SM_KB   (SM_Q  + 128 * QSTR)               // 8704
#define SM_KS   (SM_KB + 64 * KSTR)
#define SM_VB   (SM_KS + 64 * KSTR)
#define SM_VS   (SM_VB + 64 * VSTR)
#define SM_P    (SM_VS + 64 * VSTR)
#define SM_MASK (SM_P  + 8 * 16 * PSTR)            // P sized for 8 warps
#define ATTN_SMEM_BYTES ((SM_MASK + 64) * 4)       // 141,568 bytes

__global__ __launch_bounds__(256)
void attn_mma(const float* __restrict__ Q, const float* __restrict__ K,
              const float* __restrict__ V, const int* __restrict__ mask,
              const int* __restrict__ causal_p, float* __restrict__ O)
{
    extern __shared__ float smem[];
    float*    sQ  = smem + SM_Q;
    uint32_t* sKb = (uint32_t*)(smem + SM_KB);
    uint32_t* sKs = (uint32_t*)(smem + SM_KS);
    uint32_t* sVb = (uint32_t*)(smem + SM_VB);
    uint32_t* sVs = (uint32_t*)(smem + SM_VS);
    int*      sM  = (int*)(smem + SM_MASK);

    const int b   = blockIdx.z;
    const int h   = blockIdx.y;
    const int qt  = blockIdx.x;
    const int tid = threadIdx.x;
    const int lane = tid & 31;
    const int wid  = tid >> 5;       // 0..7
    const int g    = lane >> 2;
    const int tg   = lane & 3;
    const int m0   = wid * 16;       // 0..112 (< AQT=128)
    const int causal = *causal_p;

    float* sPw = smem + SM_P + wid * 16 * PSTR;

    // stage Q tile (raw fp32): 128 rows x 16 quads = 2048 float4
    const float* Qg = Q + ((size_t)(b * SEQ + qt * AQT)) * DMODEL + h * HDIM;
    #pragma unroll
    for (int j = 0; j < 8; ++j) {
        int idx = tid + j * 256;
        int r = idx >> 4, q = idx & 15;
        cp_async16(&sQ[r * QSTR + q * 4], Qg + (size_t)r * DMODEL + q * 4);
    }
    asm volatile("cp.async.commit_group;\n");

    float oacc[8][4];
    #pragma unroll
    for (int nt = 0; nt < 8; ++nt)
        #pragma unroll
        for (int c = 0; c < 4; ++c) oacc[nt][c] = 0.f;
    float mrun0 = -1e30f, mrun1 = -1e30f, l0 = 0.f, l1 = 0.f;

    const int ntiles = causal ? ((qt + 1) * (AQT / AKT)) : (SEQ / AKT);
    const float* Kg = K + ((size_t)(b * SEQ)) * DMODEL + h * HDIM;
    const float* Vg = V + ((size_t)(b * SEQ)) * DMODEL + h * HDIM;

    for (int t = 0; t < ntiles; ++t) {
        const int kbase = t * AKT;
        __syncthreads();   // previous tile's consumers done before overwrite
        #pragma unroll
        for (int j = 0; j < 4; ++j) {
            int idx = tid + j * 256;
            int r = idx >> 4, q = idx & 15;
            cp_async16(&sKb[r * KSTR + q * 4], Kg + (size_t)(kbase + r) * DMODEL + q * 4);
            cp_async16(&sVb[r * VSTR + q * 4], Vg + (size_t)(kbase + r) * DMODEL + q * 4);
        }
        if (tid < 16)
            cp_async16(&sM[tid * 4], mask + b * SEQ + kbase + tid * 4);
        asm volatile("cp.async.commit_group;\n");
        asm volatile("cp.async.wait_group 0;\n");
        __syncthreads();

        // split K,V into tf32 big/small (shared by all warps)
        #pragma unroll
        for (int j = 0; j < 16; ++j) {
            int idx = tid + j * 256;
            int r = idx >> 6, c = idx & 63;
            uint32_t bg, sl;
            tf32_split(__uint_as_float(sKb[r * KSTR + c]), bg, sl);
            sKb[r * KSTR + c] = bg; sKs[r * KSTR + c] = sl;
            tf32_split(__uint_as_float(sVb[r * VSTR + c]), bg, sl);
            sVb[r * VSTR + c] = bg; sVs[r * VSTR + c] = sl;
        }
        __syncthreads();

        // ---- S = Q K^T (3xTF32) ----
        float sacc[8][4];
        #pragma unroll
        for (int nt = 0; nt < 8; ++nt)
            #pragma unroll
            for (int c = 0; c < 4; ++c) sacc[nt][c] = 0.f;

        #pragma unroll
        for (int kt = 0; kt < 8; ++kt) {
            const int kc = kt * 8;
            uint32_t qb[4], qs[4];
            tf32_split(sQ[(m0 + g)     * QSTR + kc + tg],     qb[0], qs[0]);
            tf32_split(sQ[(m0 + g + 8) * QSTR + kc + tg],     qb[1], qs[1]);
            tf32_split(sQ[(m0 + g)     * QSTR + kc + tg + 4], qb[2], qs[2]);
            tf32_split(sQ[(m0 + g + 8) * QSTR + kc + tg + 4], qb[3], qs[3]);
            #pragma unroll
            for (int nt = 0; nt < 8; ++nt) {
                const int off = (nt * 8 + g) * KSTR + kc + tg;
                uint32_t bb0 = sKb[off], bb1 = sKb[off + 4];
                uint32_t bs0 = sKs[off], bs1 = sKs[off + 4];
                MMA_TF32(sacc[nt], qs, bb0, bb1);
                MMA_TF32(sacc[nt], qb, bs0, bs1);
                MMA_TF32(sacc[nt], qb, bb0, bb1);
            }
        }

        // ---- mask + scale + online softmax ----
        const int row0 = qt * AQT + m0 + g;
        const int row1 = row0 + 8;
        // diagonal-overlapping tile for this warp: smallest warp row is qt*AQT+m0
        const bool diag = causal && (kbase + AKT - 1 > qt * AQT + m0);
        float rmax0 = -1e30f, rmax1 = -1e30f;
        #pragma unroll
        for (int nt = 0; nt < 8; ++nt) {
            const int c0 = nt * 8 + 2 * tg;
            const int c1 = c0 + 1;
            const bool k0ok = sM[c0] != 0;
            const bool k1ok = sM[c1] != 0;
            const int gc0 = kbase + c0, gc1 = kbase + c1;
            bool v00 = k0ok && (!diag || gc0 <= row0);
            bool v01 = k1ok && (!diag || gc1 <= row0);
            bool v10 = k0ok && (!diag || gc0 <= row1);
            bool v11 = k1ok && (!diag || gc1 <= row1);
            sacc[nt][0] = v00 ? sacc[nt][0] * 0.125f : -1e30f;
            sacc[nt][1] = v01 ? sacc[nt][1] * 0.125f : -1e30f;
            sacc[nt][2] = v10 ? sacc[nt][2] * 0.125f : -1e30f;
            sacc[nt][3] = v11 ? sacc[nt][3] * 0.125f : -1e30f;
            rmax0 = fmaxf(rmax0, fmaxf(sacc[nt][0], sacc[nt][1]));
            rmax1 = fmaxf(rmax1, fmaxf(sacc[nt][2], sacc[nt][3]));
        }
        rmax0 = fmaxf(rmax0, __shfl_xor_sync(0xffffffffu, rmax0, 1));
        rmax0 = fmaxf(rmax0, __shfl_xor_sync(0xffffffffu, rmax0, 2));
        rmax1 = fmaxf(rmax1, __shfl_xor_sync(0xffffffffu, rmax1, 1));
        rmax1 = fmaxf(rmax1, __shfl_xor_sync(0xffffffffu, rmax1, 2));

        const float mnew0 = fmaxf(mrun0, rmax0);
        const float mnew1 = fmaxf(mrun1, rmax1);
        const float al0 = __expf(mrun0 - mnew0);
        const float al1 = __expf(mrun1 - mnew1);
        mrun0 = mnew0; mrun1 = mnew1;

        float rsum0 = 0.f, rsum1 = 0.f;
        #pragma unroll
        for (int nt = 0; nt < 8; ++nt) {
            float p0 = __expf(sacc[nt][0] - mnew0);
            float p1 = __expf(sacc[nt][1] - mnew0);
            float p2 = __expf(sacc[nt][2] - mnew1);
            float p3 = __expf(sacc[nt][3] - mnew1);
            rsum0 += p0 + p1;
            rsum1 += p2 + p3;
            const int c = nt * 8 + 2 * tg;
            sPw[g * PSTR + c]           = p0;
            sPw[g * PSTR + c + 1]       = p1;
            sPw[(g + 8) * PSTR + c]     = p2;
            sPw[(g + 8) * PSTR + c + 1] = p3;
        }
        rsum0 += __shfl_xor_sync(0xffffffffu, rsum0, 1);
        rsum0 += __shfl_xor_sync(0xffffffffu, rsum0, 2);
        rsum1 += __shfl_xor_sync(0xffffffffu, rsum1, 1);
        rsum1 += __shfl_xor_sync(0xffffffffu, rsum1, 2);
        l0 = l0 * al0 + rsum0;
        l1 = l1 * al1 + rsum1;

        #pragma unroll
        for (int nt = 0; nt < 8; ++nt) {
            oacc[nt][0] *= al0; oacc[nt][1] *= al0;
            oacc[nt][2] *= al1; oacc[nt][3] *= al1;
        }
        __syncwarp();

        // ---- O += P V (3xTF32) ----
        #pragma unroll
        for (int kt = 0; kt < 8; ++kt) {
            const int kc = kt * 8;
            uint32_t pb[4], ps[4];
            tf32_split(sPw[g * PSTR + kc + tg],           pb[0], ps[0]);
            tf32_split(sPw[(g + 8) * PSTR + kc + tg],     pb[1], ps[1]);
            tf32_split(sPw[g * PSTR + kc + tg + 4],       pb[2], ps[2]);
            tf32_split(sPw[(g + 8) * PSTR + kc + tg + 4], pb[3], ps[3]);
            #pragma unroll
            for (int nt = 0; nt < 8; ++nt) {
                const int off = (kc + tg) * VSTR + nt * 8 + g;
                uint32_t bb0 = sVb[off], bb1 = sVb[off + 4 * VSTR];
                uint32_t bs0 = sVs[off], bs1 = sVs[off + 4 * VSTR];
                MMA_TF32(oacc[nt], ps, bb0, bb1);
                MMA_TF32(oacc[nt], pb, bs0, bs1);
                MMA_TF32(oacc[nt], pb, bb0, bb1);
            }
        }
    }

    // ---- epilogue ----
    const float inv0 = 1.f / l0;
    const float inv1 = 1.f / l1;
    float* Og = O + ((size_t)(b * SEQ + qt * AQT + m0)) * DMODEL + h * HDIM;
    #pragma unroll
    for (int nt = 0; nt < 8; ++nt) {
        const int c = nt * 8 + 2 * tg;
        *(float2*)(Og + (size_t)g * DMODEL + c) =
            make_float2(oacc[nt][0] * inv0, oacc[nt][1] * inv0);
        *(float2*)(Og + (size_t)(g + 8) * DMODEL + c) =
            make_float2(oacc[nt][2] * inv1, oacc[nt][3] * inv1);
    }
}

// ---------------------------------------------------------------------------
// Launch
// ---------------------------------------------------------------------------
extern "C" void kernel_launch(void* const* d_in, const int* in_sizes, int n_in,
                              void* d_out, int out_size)
{
    const float* x      = (const float*)d_in[0];
    const int*   mask   = (const int*)  d_in[1];
    const int*   causal = (const int*)  d_in[2];
    const float* Wq     = (const float*)d_in[3];
    const float* Wk     = (const float*)d_in[4];
    const float* Wv     = (const float*)d_in[5];
    const float* Wo     = (const float*)d_in[6];
    float*       out    = (float*)d_out;

    float *qp, *kp, *vp, *ap;
    cudaGetSymbolAddress((void**)&qp, g_Q);
    cudaGetSymbolAddress((void**)&kp, g_K);
    cudaGetSymbolAddress((void**)&vp, g_V);
    cudaGetSymbolAddress((void**)&ap, g_A);

    static bool attr_done = false;
    if (!attr_done) {
        cudaFuncSetAttribute(tf32gemm, cudaFuncAttributeMaxDynamicSharedMemorySize,
                             GEMM_SMEM_BYTES);
        cudaFuncSetAttribute(attn_mma, cudaFuncAttributeMaxDynamicSharedMemorySize,
                             ATTN_SMEM_BYTES);
        attr_done = true;
    }

    dim3 ggrid(DMODEL / BN, MROWS / BM);   // (8, 32)
    dim3 gblk(256);

    tf32gemm<<<ggrid, gblk, GEMM_SMEM_BYTES>>>(x, Wq, qp, MROWS, DMODEL, DMODEL);
    tf32gemm<<<ggrid, gblk, GEMM_SMEM_BYTES>>>(x, Wk, kp, MROWS, DMODEL, DMODEL);
    tf32gemm<<<ggrid, gblk, GEMM_SMEM_BYTES>>>(x, Wv, vp, MROWS, DMODEL, DMODEL);

    dim3 agrid(SEQ / AQT, NHEAD, BATCH);   // (16, 16, 2)
    attn_mma<<<agrid, 256, ATTN_SMEM_BYTES>>>(qp, kp, vp, mask, causal, ap);

    tf32gemm<<<ggrid, gblk, GEMM_SMEM_BYTES>>>(ap, Wo, out, MROWS, DMODEL, DMODEL);
}

// round 10
// speedup vs baseline: 1.5161x; 1.0384x over previous
#include <cuda_runtime.h>
#include <cuda_bf16.h>
#include <math.h>
#include <stdint.h>

// ---------------------------------------------------------------------------
// Problem constants
// ---------------------------------------------------------------------------
#define BATCH   2
#define SEQ     2048
#define DMODEL  1024
#define NHEAD   16
#define HDIM    64
#define MROWS   (BATCH * SEQ)      // 4096

// ---------------------------------------------------------------------------
// Scratch
// ---------------------------------------------------------------------------
__device__ float g_Q[MROWS * DMODEL];
__device__ float g_K[MROWS * DMODEL];
__device__ float g_V[MROWS * DMODEL];
__device__ float g_A[MROWS * DMODEL];

// ---------------------------------------------------------------------------
// Common helpers
// ---------------------------------------------------------------------------
__device__ __forceinline__ void cp_async16(void* smem_dst, const void* gsrc) {
    uint32_t d = (uint32_t)__cvta_generic_to_shared(smem_dst);
    asm volatile("cp.async.cg.shared.global [%0], [%1], 16;\n" :: "r"(d), "l"(gsrc));
}

__device__ __forceinline__ void tf32_split(float a, uint32_t& big, uint32_t& small) {
    asm("cvt.rna.tf32.f32 %0, %1;\n" : "=r"(big) : "f"(a));
    float r = a - __uint_as_float(big);
    asm("cvt.rna.tf32.f32 %0, %1;\n" : "=r"(small) : "f"(r));
}

#define MMA_TF32(ACC, Afrag, B0, B1)                                        \
    asm volatile(                                                           \
        "mma.sync.aligned.m16n8k8.row.col.f32.tf32.tf32.f32 "               \
        "{%0,%1,%2,%3}, {%4,%5,%6,%7}, {%8,%9}, {%0,%1,%2,%3};\n"           \
        : "+f"(ACC[0]), "+f"(ACC[1]), "+f"(ACC[2]), "+f"(ACC[3])            \
        : "r"(Afrag[0]), "r"(Afrag[1]), "r"(Afrag[2]), "r"(Afrag[3]),       \
          "r"(B0), "r"(B1))

// ---------------------------------------------------------------------------
// 3xTF32 GEMM (unchanged — passing, rel_err 2.5e-5)
// ---------------------------------------------------------------------------
#define BM 128
#define BN 128
#define BK 32
#define ASTR 36
#define BSTR 136
#define ABUF (BM * ASTR)
#define BBUF (BK * BSTR)
#define GEMM_SMEM_BYTES ((2 * ABUF + 2 * BBUF) * 4)

__global__ __launch_bounds__(256)
void tf32gemm(const float* __restrict__ A, const float* __restrict__ Bw,
              float* __restrict__ C, int M, int N, int K)
{
    extern __shared__ float sm[];
    float* As = sm;
    float* Bs = sm + 2 * ABUF;

    const int tid  = threadIdx.x;
    const int lane = tid & 31;
    const int wid  = tid >> 5;
    const int g    = lane >> 2;
    const int tg   = lane & 3;
    const int warp_m = wid >> 2;
    const int warp_n = wid & 3;

    const int bM = blockIdx.y * BM;
    const int bN = blockIdx.x * BN;

    const float* Ag = A + (size_t)bM * K;
    const float* Bg = Bw + bN;

    float acc[4][4][4];
    #pragma unroll
    for (int i = 0; i < 4; ++i)
        #pragma unroll
        for (int j = 0; j < 4; ++j)
            #pragma unroll
            for (int c = 0; c < 4; ++c) acc[i][j][c] = 0.f;

    const int NK = K / BK;

    {
        #pragma unroll
        for (int j = 0; j < 4; ++j) {
            int idx = tid + j * 256;
            int r = idx >> 3, q = idx & 7;
            cp_async16(&As[r * ASTR + q * 4], Ag + (size_t)r * K + q * 4);
        }
        #pragma unroll
        for (int j = 0; j < 4; ++j) {
            int idx = tid + j * 256;
            int r = idx >> 5, q = idx & 31;
            cp_async16(&Bs[r * BSTR + q * 4], Bg + (size_t)r * N + q * 4);
        }
        asm volatile("cp.async.commit_group;\n");
    }

    int buf = 0;
    for (int kt = 0; kt < NK; ++kt) {
        asm volatile("cp.async.wait_group 0;\n");
        __syncthreads();

        if (kt + 1 < NK) {
            const int k0 = (kt + 1) * BK;
            const int ob = buf ^ 1;
            #pragma unroll
            for (int j = 0; j < 4; ++j) {
                int idx = tid + j * 256;
                int r = idx >> 3, q = idx & 7;
                cp_async16(&As[ob * ABUF + r * ASTR + q * 4],
                           Ag + (size_t)r * K + k0 + q * 4);
            }
            #pragma unroll
            for (int j = 0; j < 4; ++j) {
                int idx = tid + j * 256;
                int r = idx >> 5, q = idx & 31;
                cp_async16(&Bs[ob * BBUF + r * BSTR + q * 4],
                           Bg + (size_t)(k0 + r) * N + q * 4);
            }
            asm volatile("cp.async.commit_group;\n");
        }

        const float* Ab = &As[buf * ABUF + (warp_m * 64) * ASTR];
        const float* Bb = &Bs[buf * BBUF + warp_n * 32];
        #pragma unroll
        for (int ks = 0; ks < 4; ++ks) {
            const int k = ks * 8;
            uint32_t abig[4][4], asml[4][4], bbig[4][2], bsml[4][2];
            #pragma unroll
            for (int mt = 0; mt < 4; ++mt) {
                const float* p = Ab + (mt * 16 + g) * ASTR + k + tg;
                tf32_split(p[0],            abig[mt][0], asml[mt][0]);
                tf32_split(p[8 * ASTR],     abig[mt][1], asml[mt][1]);
                tf32_split(p[4],            abig[mt][2], asml[mt][2]);
                tf32_split(p[8 * ASTR + 4], abig[mt][3], asml[mt][3]);
            }
            #pragma unroll
            for (int nt = 0; nt < 4; ++nt) {
                const float* p = Bb + (k + tg) * BSTR + nt * 8 + g;
                tf32_split(p[0],        bbig[nt][0], bsml[nt][0]);
                tf32_split(p[4 * BSTR], bbig[nt][1], bsml[nt][1]);
            }
            #pragma unroll
            for (int mt = 0; mt < 4; ++mt)
                #pragma unroll
                for (int nt = 0; nt < 4; ++nt) {
                    MMA_TF32(acc[mt][nt], asml[mt], bbig[nt][0], bbig[nt][1]);
                    MMA_TF32(acc[mt][nt], abig[mt], bsml[nt][0], bsml[nt][1]);
                    MMA_TF32(acc[mt][nt], abig[mt], bbig[nt][0], bbig[nt][1]);
                }
        }
        __syncthreads();
        buf ^= 1;
    }

    float* Cb = C + (size_t)(bM + warp_m * 64) * N + bN + warp_n * 32;
    #pragma unroll
    for (int mt = 0; mt < 4; ++mt) {
        #pragma unroll
        for (int nt = 0; nt < 4; ++nt) {
            float* p0 = Cb + (size_t)(mt * 16 + g) * N + nt * 8 + 2 * tg;
            float* p1 = Cb + (size_t)(mt * 16 + g + 8) * N + nt * 8 + 2 * tg;
            *(float2*)p0 = make_float2(acc[mt][nt][0], acc[mt][nt][1]);
            *(float2*)p1 = make_float2(acc[mt][nt][2], acc[mt][nt][3]);
        }
    }
}

// ---------------------------------------------------------------------------
// Tensor-core flash attention (3xTF32, m16n8k8).
// Block: 128 queries of one (b,h); 8 warps x 16 query rows. 256 threads.
// K/V stored RAW in smem; tf32 big/small split happens at fragment load in
// registers (no split phase, no split buffers) -> 105.7KB smem -> 2 CTA/SM.
// ---------------------------------------------------------------------------
#define AQT  128
#define AKT  64
#define QSTR 68            // (4g+tg)%32 conflict-free for A-frag loads
#define KSTR 68
#define VSTR 72            // (8tg+g)%32 conflict-free for B-frag loads
#define PSTR 68

#define SM_Q    0
#define SM_K    (SM_Q + 128 * QSTR)
#define SM_V    (SM_K + 64 * KSTR)
#define SM_P    (SM_V + 64 * VSTR)
#define SM_MASK (SM_P + 8 * 16 * PSTR)
#define ATTN_SMEM_BYTES ((SM_MASK + 64) * 4)       // 105,984 bytes

__global__ __launch_bounds__(256, 2)
void attn_mma(const float* __restrict__ Q, const float* __restrict__ K,
              const float* __restrict__ V, const int* __restrict__ mask,
              const int* __restrict__ causal_p, float* __restrict__ O)
{
    extern __shared__ float smem[];
    float* sQ = smem + SM_Q;
    float* sK = smem + SM_K;
    float* sV = smem + SM_V;
    int*   sM = (int*)(smem + SM_MASK);

    const int b   = blockIdx.z;
    const int h   = blockIdx.y;
    const int qt  = blockIdx.x;
    const int tid = threadIdx.x;
    const int lane = tid & 31;
    const int wid  = tid >> 5;       // 0..7
    const int g    = lane >> 2;
    const int tg   = lane & 3;
    const int m0   = wid * 16;
    const int causal = *causal_p;

    float* sPw = smem + SM_P + wid * 16 * PSTR;

    // stage Q tile (raw fp32): 128 rows x 16 quads
    const float* Qg = Q + ((size_t)(b * SEQ + qt * AQT)) * DMODEL + h * HDIM;
    #pragma unroll
    for (int j = 0; j < 8; ++j) {
        int idx = tid + j * 256;
        int r = idx >> 4, q = idx & 15;
        cp_async16(&sQ[r * QSTR + q * 4], Qg + (size_t)r * DMODEL + q * 4);
    }
    asm volatile("cp.async.commit_group;\n");

    float oacc[8][4];
    #pragma unroll
    for (int nt = 0; nt < 8; ++nt)
        #pragma unroll
        for (int c = 0; c < 4; ++c) oacc[nt][c] = 0.f;
    float mrun0 = -1e30f, mrun1 = -1e30f, l0 = 0.f, l1 = 0.f;

    const int ntiles = causal ? ((qt + 1) * (AQT / AKT)) : (SEQ / AKT);
    const float* Kg = K + ((size_t)(b * SEQ)) * DMODEL + h * HDIM;
    const float* Vg = V + ((size_t)(b * SEQ)) * DMODEL + h * HDIM;

    for (int t = 0; t < ntiles; ++t) {
        const int kbase = t * AKT;
        __syncthreads();   // previous tile's consumers done before overwrite
        #pragma unroll
        for (int j = 0; j < 4; ++j) {
            int idx = tid + j * 256;
            int r = idx >> 4, q = idx & 15;
            cp_async16(&sK[r * KSTR + q * 4], Kg + (size_t)(kbase + r) * DMODEL + q * 4);
            cp_async16(&sV[r * VSTR + q * 4], Vg + (size_t)(kbase + r) * DMODEL + q * 4);
        }
        if (tid < 16)
            cp_async16(&sM[tid * 4], mask + b * SEQ + kbase + tid * 4);
        asm volatile("cp.async.commit_group;\n");
        asm volatile("cp.async.wait_group 0;\n");
        __syncthreads();

        // ---- S = Q K^T (3xTF32), K split in registers ----
        float sacc[8][4];
        #pragma unroll
        for (int nt = 0; nt < 8; ++nt)
            #pragma unroll
            for (int c = 0; c < 4; ++c) sacc[nt][c] = 0.f;

        #pragma unroll
        for (int kt = 0; kt < 8; ++kt) {
            const int kc = kt * 8;
            uint32_t qb[4], qs[4];
            tf32_split(sQ[(m0 + g)     * QSTR + kc + tg],     qb[0], qs[0]);
            tf32_split(sQ[(m0 + g + 8) * QSTR + kc + tg],     qb[1], qs[1]);
            tf32_split(sQ[(m0 + g)     * QSTR + kc + tg + 4], qb[2], qs[2]);
            tf32_split(sQ[(m0 + g + 8) * QSTR + kc + tg + 4], qb[3], qs[3]);
            #pragma unroll
            for (int nt = 0; nt < 8; ++nt) {
                const int off = (nt * 8 + g) * KSTR + kc + tg;
                uint32_t bb0, bs0, bb1, bs1;
                tf32_split(sK[off],     bb0, bs0);
                tf32_split(sK[off + 4], bb1, bs1);
                MMA_TF32(sacc[nt], qs, bb0, bb1);
                MMA_TF32(sacc[nt], qb, bs0, bs1);
                MMA_TF32(sacc[nt], qb, bb0, bb1);
            }
        }

        // ---- mask + scale + online softmax ----
        const int row0 = qt * AQT + m0 + g;
        const int row1 = row0 + 8;
        const bool diag = causal && (kbase + AKT - 1 > qt * AQT + m0);
        float rmax0 = -1e30f, rmax1 = -1e30f;
        #pragma unroll
        for (int nt = 0; nt < 8; ++nt) {
            const int c0 = nt * 8 + 2 * tg;
            const int c1 = c0 + 1;
            const bool k0ok = sM[c0] != 0;
            const bool k1ok = sM[c1] != 0;
            const int gc0 = kbase + c0, gc1 = kbase + c1;
            bool v00 = k0ok && (!diag || gc0 <= row0);
            bool v01 = k1ok && (!diag || gc1 <= row0);
            bool v10 = k0ok && (!diag || gc0 <= row1);
            bool v11 = k1ok && (!diag || gc1 <= row1);
            sacc[nt][0] = v00 ? sacc[nt][0] * 0.125f : -1e30f;
            sacc[nt][1] = v01 ? sacc[nt][1] * 0.125f : -1e30f;
            sacc[nt][2] = v10 ? sacc[nt][2] * 0.125f : -1e30f;
            sacc[nt][3] = v11 ? sacc[nt][3] * 0.125f : -1e30f;
            rmax0 = fmaxf(rmax0, fmaxf(sacc[nt][0], sacc[nt][1]));
            rmax1 = fmaxf(rmax1, fmaxf(sacc[nt][2], sacc[nt][3]));
        }
        rmax0 = fmaxf(rmax0, __shfl_xor_sync(0xffffffffu, rmax0, 1));
        rmax0 = fmaxf(rmax0, __shfl_xor_sync(0xffffffffu, rmax0, 2));
        rmax1 = fmaxf(rmax1, __shfl_xor_sync(0xffffffffu, rmax1, 1));
        rmax1 = fmaxf(rmax1, __shfl_xor_sync(0xffffffffu, rmax1, 2));

        const float mnew0 = fmaxf(mrun0, rmax0);
        const float mnew1 = fmaxf(mrun1, rmax1);
        const float al0 = __expf(mrun0 - mnew0);
        const float al1 = __expf(mrun1 - mnew1);
        mrun0 = mnew0; mrun1 = mnew1;

        float rsum0 = 0.f, rsum1 = 0.f;
        #pragma unroll
        for (int nt = 0; nt < 8; ++nt) {
            float p0 = __expf(sacc[nt][0] - mnew0);
            float p1 = __expf(sacc[nt][1] - mnew0);
            float p2 = __expf(sacc[nt][2] - mnew1);
            float p3 = __expf(sacc[nt][3] - mnew1);
            rsum0 += p0 + p1;
            rsum1 += p2 + p3;
            const int c = nt * 8 + 2 * tg;
            sPw[g * PSTR + c]           = p0;
            sPw[g * PSTR + c + 1]       = p1;
            sPw[(g + 8) * PSTR + c]     = p2;
            sPw[(g + 8) * PSTR + c + 1] = p3;
        }
        rsum0 += __shfl_xor_sync(0xffffffffu, rsum0, 1);
        rsum0 += __shfl_xor_sync(0xffffffffu, rsum0, 2);
        rsum1 += __shfl_xor_sync(0xffffffffu, rsum1, 1);
        rsum1 += __shfl_xor_sync(0xffffffffu, rsum1, 2);
        l0 = l0 * al0 + rsum0;
        l1 = l1 * al1 + rsum1;

        #pragma unroll
        for (int nt = 0; nt < 8; ++nt) {
            oacc[nt][0] *= al0; oacc[nt][1] *= al0;
            oacc[nt][2] *= al1; oacc[nt][3] *= al1;
        }
        __syncwarp();

        // ---- O += P V (3xTF32), V split in registers ----
        #pragma unroll
        for (int kt = 0; kt < 8; ++kt) {
            const int kc = kt * 8;
            uint32_t pb[4], ps[4];
            tf32_split(sPw[g * PSTR + kc + tg],           pb[0], ps[0]);
            tf32_split(sPw[(g + 8) * PSTR + kc + tg],     pb[1], ps[1]);
            tf32_split(sPw[g * PSTR + kc + tg + 4],       pb[2], ps[2]);
            tf32_split(sPw[(g + 8) * PSTR + kc + tg + 4], pb[3], ps[3]);
            #pragma unroll
            for (int nt = 0; nt < 8; ++nt) {
                const int off = (kc + tg) * VSTR + nt * 8 + g;
                uint32_t bb0, bs0, bb1, bs1;
                tf32_split(sV[off],            bb0, bs0);
                tf32_split(sV[off + 4 * VSTR], bb1, bs1);
                MMA_TF32(oacc[nt], ps, bb0, bb1);
                MMA_TF32(oacc[nt], pb, bs0, bs1);
                MMA_TF32(oacc[nt], pb, bb0, bb1);
            }
        }
    }

    // ---- epilogue ----
    const float inv0 = 1.f / l0;
    const float inv1 = 1.f / l1;
    float* Og = O + ((size_t)(b * SEQ + qt * AQT + m0)) * DMODEL + h * HDIM;
    #pragma unroll
    for (int nt = 0; nt < 8; ++nt) {
        const int c = nt * 8 + 2 * tg;
        *(float2*)(Og + (size_t)g * DMODEL + c) =
            make_float2(oacc[nt][0] * inv0, oacc[nt][1] * inv0);
        *(float2*)(Og + (size_t)(g + 8) * DMODEL + c) =
            make_float2(oacc[nt][2] * inv1, oacc[nt][3] * inv1);
    }
}

// ---------------------------------------------------------------------------
// Launch
// ---------------------------------------------------------------------------
extern "C" void kernel_launch(void* const* d_in, const int* in_sizes, int n_in,
                              void* d_out, int out_size)
{
    const float* x      = (const float*)d_in[0];
    const int*   mask   = (const int*)  d_in[1];
    const int*   causal = (const int*)  d_in[2];
    const float* Wq     = (const float*)d_in[3];
    const float* Wk     = (const float*)d_in[4];
    const float* Wv     = (const float*)d_in[5];
    const float* Wo     = (const float*)d_in[6];
    float*       out    = (float*)d_out;

    float *qp, *kp, *vp, *ap;
    cudaGetSymbolAddress((void**)&qp, g_Q);
    cudaGetSymbolAddress((void**)&kp, g_K);
    cudaGetSymbolAddress((void**)&vp, g_V);
    cudaGetSymbolAddress((void**)&ap, g_A);

    static bool attr_done = false;
    if (!attr_done) {
        cudaFuncSetAttribute(tf32gemm, cudaFuncAttributeMaxDynamicSharedMemorySize,
                             GEMM_SMEM_BYTES);
        cudaFuncSetAttribute(attn_mma, cudaFuncAttributeMaxDynamicSharedMemorySize,
                             ATTN_SMEM_BYTES);
        attr_done = true;
    }

    dim3 ggrid(DMODEL / BN, MROWS / BM);   // (8, 32)
    dim3 gblk(256);

    tf32gemm<<<ggrid, gblk, GEMM_SMEM_BYTES>>>(x, Wq, qp, MROWS, DMODEL, DMODEL);
    tf32gemm<<<ggrid, gblk, GEMM_SMEM_BYTES>>>(x, Wk, kp, MROWS, DMODEL, DMODEL);
    tf32gemm<<<ggrid, gblk, GEMM_SMEM_BYTES>>>(x, Wv, vp, MROWS, DMODEL, DMODEL);

    dim3 agrid(SEQ / AQT, NHEAD, BATCH);   // (16, 16, 2)
    attn_mma<<<agrid, 256, ATTN_SMEM_BYTES>>>(qp, kp, vp, mask, causal, ap);

    tf32gemm<<<ggrid, gblk, GEMM_SMEM_BYTES>>>(ap, Wo, out, MROWS, DMODEL, DMODEL);
}

// round 11
// speedup vs baseline: 2.0391x; 1.3450x over previous
#include <cuda_runtime.h>
#include <cuda_bf16.h>
#include <math.h>
#include <stdint.h>

// ---------------------------------------------------------------------------
// Problem constants
// ---------------------------------------------------------------------------
#define BATCH   2
#define SEQ     2048
#define DMODEL  1024
#define NHEAD   16
#define HDIM    64
#define MROWS   (BATCH * SEQ)      // 4096

// ---------------------------------------------------------------------------
// Scratch
// ---------------------------------------------------------------------------
__device__ float g_Q[MROWS * DMODEL];
__device__ float g_K[MROWS * DMODEL];
__device__ float g_V[MROWS * DMODEL];
__device__ float g_A[MROWS * DMODEL];

// ---------------------------------------------------------------------------
// Common helpers
// ---------------------------------------------------------------------------
__device__ __forceinline__ void cp_async16(void* smem_dst, const void* gsrc) {
    uint32_t d = (uint32_t)__cvta_generic_to_shared(smem_dst);
    asm volatile("cp.async.cg.shared.global [%0], [%1], 16;\n" :: "r"(d), "l"(gsrc));
}

__device__ __forceinline__ void tf32_split(float a, uint32_t& big, uint32_t& small) {
    asm("cvt.rna.tf32.f32 %0, %1;\n" : "=r"(big) : "f"(a));
    float r = a - __uint_as_float(big);
    asm("cvt.rna.tf32.f32 %0, %1;\n" : "=r"(small) : "f"(r));
}

#define MMA_TF32(ACC, Afrag, B0, B1)                                        \
    asm volatile(                                                           \
        "mma.sync.aligned.m16n8k8.row.col.f32.tf32.tf32.f32 "               \
        "{%0,%1,%2,%3}, {%4,%5,%6,%7}, {%8,%9}, {%0,%1,%2,%3};\n"           \
        : "+f"(ACC[0]), "+f"(ACC[1]), "+f"(ACC[2]), "+f"(ACC[3])            \
        : "r"(Afrag[0]), "r"(Afrag[1]), "r"(Afrag[2]), "r"(Afrag[3]),       \
          "r"(B0), "r"(B1))

// ---- bf16 hi/lo helpers -----------------------------------------------------
// pack2(e0,e1): e0 -> lower half, e1 -> upper half (first PTX source = upper)
__device__ __forceinline__ uint32_t pack_bf16(float e0, float e1) {
    uint32_t r;
    asm("cvt.rn.bf16x2.f32 %0, %1, %2;\n" : "=r"(r) : "f"(e1), "f"(e0));
    return r;
}
__device__ __forceinline__ float bf16_lo_f(uint32_t w) { return __uint_as_float(w << 16); }
__device__ __forceinline__ float bf16_hi_f(uint32_t w) { return __uint_as_float(w & 0xffff0000u); }
// split pair (e0,e1) into packed hi word + packed lo-residual word
__device__ __forceinline__ void bf16x3_split(float e0, float e1, uint32_t& hi, uint32_t& lo) {
    hi = pack_bf16(e0, e1);
    float r0 = e0 - bf16_lo_f(hi);
    float r1 = e1 - bf16_hi_f(hi);
    lo = pack_bf16(r0, r1);
}

#define MMA_BF16(ACC, A0, A1, A2, A3, B0, B1)                               \
    asm volatile(                                                           \
        "mma.sync.aligned.m16n8k16.row.col.f32.bf16.bf16.f32 "              \
        "{%0,%1,%2,%3}, {%4,%5,%6,%7}, {%8,%9}, {%0,%1,%2,%3};\n"           \
        : "+f"(ACC[0]), "+f"(ACC[1]), "+f"(ACC[2]), "+f"(ACC[3])            \
        : "r"(A0), "r"(A1), "r"(A2), "r"(A3), "r"(B0), "r"(B1))

// ---------------------------------------------------------------------------
// 3xTF32 GEMM (unchanged — passing, rel_err 2.5e-5)
// ---------------------------------------------------------------------------
#define BM 128
#define BN 128
#define BK 32
#define ASTR 36
#define BSTR 136
#define ABUF (BM * ASTR)
#define BBUF (BK * BSTR)
#define GEMM_SMEM_BYTES ((2 * ABUF + 2 * BBUF) * 4)

__global__ __launch_bounds__(256)
void tf32gemm(const float* __restrict__ A, const float* __restrict__ Bw,
              float* __restrict__ C, int M, int N, int K)
{
    extern __shared__ float sm[];
    float* As = sm;
    float* Bs = sm + 2 * ABUF;

    const int tid  = threadIdx.x;
    const int lane = tid & 31;
    const int wid  = tid >> 5;
    const int g    = lane >> 2;
    const int tg   = lane & 3;
    const int warp_m = wid >> 2;
    const int warp_n = wid & 3;

    const int bM = blockIdx.y * BM;
    const int bN = blockIdx.x * BN;

    const float* Ag = A + (size_t)bM * K;
    const float* Bg = Bw + bN;

    float acc[4][4][4];
    #pragma unroll
    for (int i = 0; i < 4; ++i)
        #pragma unroll
        for (int j = 0; j < 4; ++j)
            #pragma unroll
            for (int c = 0; c < 4; ++c) acc[i][j][c] = 0.f;

    const int NK = K / BK;

    {
        #pragma unroll
        for (int j = 0; j < 4; ++j) {
            int idx = tid + j * 256;
            int r = idx >> 3, q = idx & 7;
            cp_async16(&As[r * ASTR + q * 4], Ag + (size_t)r * K + q * 4);
        }
        #pragma unroll
        for (int j = 0; j < 4; ++j) {
            int idx = tid + j * 256;
            int r = idx >> 5, q = idx & 31;
            cp_async16(&Bs[r * BSTR + q * 4], Bg + (size_t)r * N + q * 4);
        }
        asm volatile("cp.async.commit_group;\n");
    }

    int buf = 0;
    for (int kt = 0; kt < NK; ++kt) {
        asm volatile("cp.async.wait_group 0;\n");
        __syncthreads();

        if (kt + 1 < NK) {
            const int k0 = (kt + 1) * BK;
            const int ob = buf ^ 1;
            #pragma unroll
            for (int j = 0; j < 4; ++j) {
                int idx = tid + j * 256;
                int r = idx >> 3, q = idx & 7;
                cp_async16(&As[ob * ABUF + r * ASTR + q * 4],
                           Ag + (size_t)r * K + k0 + q * 4);
            }
            #pragma unroll
            for (int j = 0; j < 4; ++j) {
                int idx = tid + j * 256;
                int r = idx >> 5, q = idx & 31;
                cp_async16(&Bs[ob * BBUF + r * BSTR + q * 4],
                           Bg + (size_t)(k0 + r) * N + q * 4);
            }
            asm volatile("cp.async.commit_group;\n");
        }

        const float* Ab = &As[buf * ABUF + (warp_m * 64) * ASTR];
        const float* Bb = &Bs[buf * BBUF + warp_n * 32];
        #pragma unroll
        for (int ks = 0; ks < 4; ++ks) {
            const int k = ks * 8;
            uint32_t abig[4][4], asml[4][4], bbig[4][2], bsml[4][2];
            #pragma unroll
            for (int mt = 0; mt < 4; ++mt) {
                const float* p = Ab + (mt * 16 + g) * ASTR + k + tg;
                tf32_split(p[0],            abig[mt][0], asml[mt][0]);
                tf32_split(p[8 * ASTR],     abig[mt][1], asml[mt][1]);
                tf32_split(p[4],            abig[mt][2], asml[mt][2]);
                tf32_split(p[8 * ASTR + 4], abig[mt][3], asml[mt][3]);
            }
            #pragma unroll
            for (int nt = 0; nt < 4; ++nt) {
                const float* p = Bb + (k + tg) * BSTR + nt * 8 + g;
                tf32_split(p[0],        bbig[nt][0], bsml[nt][0]);
                tf32_split(p[4 * BSTR], bbig[nt][1], bsml[nt][1]);
            }
            #pragma unroll
            for (int mt = 0; mt < 4; ++mt)
                #pragma unroll
                for (int nt = 0; nt < 4; ++nt) {
                    MMA_TF32(acc[mt][nt], asml[mt], bbig[nt][0], bbig[nt][1]);
                    MMA_TF32(acc[mt][nt], abig[mt], bsml[nt][0], bsml[nt][1]);
                    MMA_TF32(acc[mt][nt], abig[mt], bbig[nt][0], bbig[nt][1]);
                }
        }
        __syncthreads();
        buf ^= 1;
    }

    float* Cb = C + (size_t)(bM + warp_m * 64) * N + bN + warp_n * 32;
    #pragma unroll
    for (int mt = 0; mt < 4; ++mt) {
        #pragma unroll
        for (int nt = 0; nt < 4; ++nt) {
            float* p0 = Cb + (size_t)(mt * 16 + g) * N + nt * 8 + 2 * tg;
            float* p1 = Cb + (size_t)(mt * 16 + g + 8) * N + nt * 8 + 2 * tg;
            *(float2*)p0 = make_float2(acc[mt][nt][0], acc[mt][nt][1]);
            *(float2*)p1 = make_float2(acc[mt][nt][2], acc[mt][nt][3]);
        }
    }
}

// ---------------------------------------------------------------------------
// bf16x3 tensor-core flash attention (m16n8k16, hi/lo error compensation).
// Block: 128 queries of one (b,h); 8 warps x 16 rows; 256 threads; 2 CTA/SM.
// Q/K/V stored in smem as packed bf16 hi + lo words (split once per tile).
// P never touches smem: C-frag pairs ARE the next A-frag pairs.
// ---------------------------------------------------------------------------
#define AQT  128
#define AKT  64
#define QSTRW 36           // words per Q row  (32 + 4 pad): banks 4g+tg
#define KSTRW 36           // words per K row
#define VSTRW 72           // words per V k'-row (64 + 8 pad): banks 8tg+g

#define SM_QH   0
#define SM_QL   (SM_QH + 128 * QSTRW)      // 4608
#define SM_KH   (SM_QL + 128 * QSTRW)      // 9216
#define SM_KL   (SM_KH + 64 * KSTRW)       // 11520
#define SM_VH   (SM_KL + 64 * KSTRW)       // 13824
#define SM_VL   (SM_VH + 32 * VSTRW)       // 16128
#define SM_MSK  (SM_VL + 32 * VSTRW)       // 18432
#define ATTN_SMEM_BYTES ((SM_MSK + 64 + 16) * 4)   // 74,048 bytes

__global__ __launch_bounds__(256, 2)
void attn_mma(const float* __restrict__ Q, const float* __restrict__ K,
              const float* __restrict__ V, const int* __restrict__ mask,
              const int* __restrict__ causal_p, float* __restrict__ O)
{
    extern __shared__ uint32_t smw[];
    uint32_t* sQh = smw + SM_QH;
    uint32_t* sQl = smw + SM_QL;
    uint32_t* sKh = smw + SM_KH;
    uint32_t* sKl = smw + SM_KL;
    uint32_t* sVh = smw + SM_VH;
    uint32_t* sVl = smw + SM_VL;
    int*      sM  = (int*)(smw + SM_MSK);

    const int b   = blockIdx.z;
    const int h   = blockIdx.y;
    const int qt  = blockIdx.x;
    const int tid = threadIdx.x;
    const int lane = tid & 31;
    const int wid  = tid >> 5;       // 0..7
    const int g    = lane >> 2;
    const int tg   = lane & 3;
    const int m0   = wid * 16;
    const int causal = *causal_p;

    // ---- Q tile: load + split to packed bf16 hi/lo (once) ----
    const float* Qg = Q + ((size_t)(b * SEQ + qt * AQT)) * DMODEL + h * HDIM;
    #pragma unroll
    for (int j = 0; j < 8; ++j) {
        int idx = tid + j * 256;
        int r = idx >> 4, cq = idx & 15;
        float4 qv = *(const float4*)(Qg + (size_t)r * DMODEL + cq * 4);
        uint32_t h0, l0, h1, l1;
        bf16x3_split(qv.x, qv.y, h0, l0);
        bf16x3_split(qv.z, qv.w, h1, l1);
        sQh[r * QSTRW + cq * 2]     = h0;
        sQh[r * QSTRW + cq * 2 + 1] = h1;
        sQl[r * QSTRW + cq * 2]     = l0;
        sQl[r * QSTRW + cq * 2 + 1] = l1;
    }

    float oacc[8][4];
    #pragma unroll
    for (int nt = 0; nt < 8; ++nt)
        #pragma unroll
        for (int c = 0; c < 4; ++c) oacc[nt][c] = 0.f;
    float mrun0 = -1e30f, mrun1 = -1e30f, l0s = 0.f, l1s = 0.f;

    const int ntiles = causal ? ((qt + 1) * (AQT / AKT)) : (SEQ / AKT);
    const float* Kg = K + ((size_t)(b * SEQ)) * DMODEL + h * HDIM;
    const float* Vg = V + ((size_t)(b * SEQ)) * DMODEL + h * HDIM;

    for (int t = 0; t < ntiles; ++t) {
        const int kbase = t * AKT;
        __syncthreads();   // previous tile's consumers done before overwrite

        // ---- K tile: 64 rows x 64 cols -> packed hi/lo (row-adjacent pairs) ----
        #pragma unroll
        for (int j = 0; j < 4; ++j) {
            int idx = tid + j * 256;
            int r = idx >> 4, cq = idx & 15;
            float4 kv = *(const float4*)(Kg + (size_t)(kbase + r) * DMODEL + cq * 4);
            uint32_t h0, lo0, h1, lo1;
            bf16x3_split(kv.x, kv.y, h0, lo0);
            bf16x3_split(kv.z, kv.w, h1, lo1);
            sKh[r * KSTRW + cq * 2]     = h0;
            sKh[r * KSTRW + cq * 2 + 1] = h1;
            sKl[r * KSTRW + cq * 2]     = lo0;
            sKl[r * KSTRW + cq * 2 + 1] = lo1;
        }
        // ---- V tile: pack pairs ACROSS key rows: word = {V[2k'][n], V[2k'+1][n]} ----
        #pragma unroll
        for (int j = 0; j < 2; ++j) {
            int idx = tid + j * 256;
            int kp = idx >> 4, cq = idx & 15;      // key-pair 0..31, col-quad 0..15
            const float* v0 = Vg + (size_t)(kbase + 2 * kp) * DMODEL + cq * 4;
            float4 a = *(const float4*)v0;
            float4 bb = *(const float4*)(v0 + DMODEL);
            uint32_t hh, ll;
            bf16x3_split(a.x, bb.x, hh, ll);
            sVh[kp * VSTRW + cq * 4 + 0] = hh; sVl[kp * VSTRW + cq * 4 + 0] = ll;
            bf16x3_split(a.y, bb.y, hh, ll);
            sVh[kp * VSTRW + cq * 4 + 1] = hh; sVl[kp * VSTRW + cq * 4 + 1] = ll;
            bf16x3_split(a.z, bb.z, hh, ll);
            sVh[kp * VSTRW + cq * 4 + 2] = hh; sVl[kp * VSTRW + cq * 4 + 2] = ll;
            bf16x3_split(a.w, bb.w, hh, ll);
            sVh[kp * VSTRW + cq * 4 + 3] = hh; sVl[kp * VSTRW + cq * 4 + 3] = ll;
        }
        if (tid < AKT) sM[tid] = mask[b * SEQ + kbase + tid];
        __syncthreads();

        // ---- S = Q K^T (bf16x3, m16n8k16) ----
        float sacc[8][4];
        #pragma unroll
        for (int nt = 0; nt < 8; ++nt)
            #pragma unroll
            for (int c = 0; c < 4; ++c) sacc[nt][c] = 0.f;

        #pragma unroll
        for (int kt = 0; kt < 4; ++kt) {           // 4 x k16 over HDIM=64
            const int kw = 8 * kt + tg;
            uint32_t qh0 = sQh[(m0 + g) * QSTRW + kw];
            uint32_t qh1 = sQh[(m0 + g + 8) * QSTRW + kw];
            uint32_t qh2 = sQh[(m0 + g) * QSTRW + kw + 4];
            uint32_t qh3 = sQh[(m0 + g + 8) * QSTRW + kw + 4];
            uint32_t ql0 = sQl[(m0 + g) * QSTRW + kw];
            uint32_t ql1 = sQl[(m0 + g + 8) * QSTRW + kw];
            uint32_t ql2 = sQl[(m0 + g) * QSTRW + kw + 4];
            uint32_t ql3 = sQl[(m0 + g + 8) * QSTRW + kw + 4];
            #pragma unroll
            for (int nt = 0; nt < 8; ++nt) {
                const int ka = (nt * 8 + g) * KSTRW + kw;
                uint32_t bh0 = sKh[ka], bh1 = sKh[ka + 4];
                uint32_t bl0 = sKl[ka], bl1 = sKl[ka + 4];
                MMA_BF16(sacc[nt], ql0, ql1, ql2, ql3, bh0, bh1);
                MMA_BF16(sacc[nt], qh0, qh1, qh2, qh3, bl0, bl1);
                MMA_BF16(sacc[nt], qh0, qh1, qh2, qh3, bh0, bh1);
            }
        }

        // ---- mask + scale + online softmax (p stays in sacc registers) ----
        const int row0 = qt * AQT + m0 + g;
        const int row1 = row0 + 8;
        const bool diag = causal && (kbase + AKT - 1 > qt * AQT + m0);
        float rmax0 = -1e30f, rmax1 = -1e30f;
        #pragma unroll
        for (int nt = 0; nt < 8; ++nt) {
            const int c0 = nt * 8 + 2 * tg;
            const int c1 = c0 + 1;
            const bool k0ok = sM[c0] != 0;
            const bool k1ok = sM[c1] != 0;
            const int gc0 = kbase + c0, gc1 = kbase + c1;
            bool v00 = k0ok && (!diag || gc0 <= row0);
            bool v01 = k1ok && (!diag || gc1 <= row0);
            bool v10 = k0ok && (!diag || gc0 <= row1);
            bool v11 = k1ok && (!diag || gc1 <= row1);
            sacc[nt][0] = v00 ? sacc[nt][0] * 0.125f : -1e30f;
            sacc[nt][1] = v01 ? sacc[nt][1] * 0.125f : -1e30f;
            sacc[nt][2] = v10 ? sacc[nt][2] * 0.125f : -1e30f;
            sacc[nt][3] = v11 ? sacc[nt][3] * 0.125f : -1e30f;
            rmax0 = fmaxf(rmax0, fmaxf(sacc[nt][0], sacc[nt][1]));
            rmax1 = fmaxf(rmax1, fmaxf(sacc[nt][2], sacc[nt][3]));
        }
        rmax0 = fmaxf(rmax0, __shfl_xor_sync(0xffffffffu, rmax0, 1));
        rmax0 = fmaxf(rmax0, __shfl_xor_sync(0xffffffffu, rmax0, 2));
        rmax1 = fmaxf(rmax1, __shfl_xor_sync(0xffffffffu, rmax1, 1));
        rmax1 = fmaxf(rmax1, __shfl_xor_sync(0xffffffffu, rmax1, 2));

        const float mnew0 = fmaxf(mrun0, rmax0);
        const float mnew1 = fmaxf(mrun1, rmax1);
        const float al0 = __expf(mrun0 - mnew0);
        const float al1 = __expf(mrun1 - mnew1);
        mrun0 = mnew0; mrun1 = mnew1;

        float rsum0 = 0.f, rsum1 = 0.f;
        #pragma unroll
        for (int nt = 0; nt < 8; ++nt) {
            sacc[nt][0] = __expf(sacc[nt][0] - mnew0);
            sacc[nt][1] = __expf(sacc[nt][1] - mnew0);
            sacc[nt][2] = __expf(sacc[nt][2] - mnew1);
            sacc[nt][3] = __expf(sacc[nt][3] - mnew1);
            rsum0 += sacc[nt][0] + sacc[nt][1];
            rsum1 += sacc[nt][2] + sacc[nt][3];
        }
        rsum0 += __shfl_xor_sync(0xffffffffu, rsum0, 1);
        rsum0 += __shfl_xor_sync(0xffffffffu, rsum0, 2);
        rsum1 += __shfl_xor_sync(0xffffffffu, rsum1, 1);
        rsum1 += __shfl_xor_sync(0xffffffffu, rsum1, 2);
        l0s = l0s * al0 + rsum0;
        l1s = l1s * al1 + rsum1;

        #pragma unroll
        for (int nt = 0; nt < 8; ++nt) {
            oacc[nt][0] *= al0; oacc[nt][1] *= al0;
            oacc[nt][2] *= al1; oacc[nt][3] *= al1;
        }

        // ---- O += P V (bf16x3, m16n8k16); P A-frags packed from registers ----
        #pragma unroll
        for (int kt = 0; kt < 4; ++kt) {           // 4 x k16 over 64 keys
            uint32_t ph0, pl0, ph1, pl1, ph2, pl2, ph3, pl3;
            bf16x3_split(sacc[2 * kt][0],     sacc[2 * kt][1],     ph0, pl0);
            bf16x3_split(sacc[2 * kt][2],     sacc[2 * kt][3],     ph1, pl1);
            bf16x3_split(sacc[2 * kt + 1][0], sacc[2 * kt + 1][1], ph2, pl2);
            bf16x3_split(sacc[2 * kt + 1][2], sacc[2 * kt + 1][3], ph3, pl3);
            #pragma unroll
            for (int nt = 0; nt < 8; ++nt) {
                const int va = (8 * kt + tg) * VSTRW + nt * 8 + g;
                uint32_t bh0 = sVh[va], bh1 = sVh[va + 4 * VSTRW];
                uint32_t bl0 = sVl[va], bl1 = sVl[va + 4 * VSTRW];
                MMA_BF16(oacc[nt], pl0, pl1, pl2, pl3, bh0, bh1);
                MMA_BF16(oacc[nt], ph0, ph1, ph2, ph3, bl0, bl1);
                MMA_BF16(oacc[nt], ph0, ph1, ph2, ph3, bh0, bh1);
            }
        }
    }

    // ---- epilogue ----
    const float inv0 = 1.f / l0s;
    const float inv1 = 1.f / l1s;
    float* Og = O + ((size_t)(b * SEQ + qt * AQT + m0)) * DMODEL + h * HDIM;
    #pragma unroll
    for (int nt = 0; nt < 8; ++nt) {
        const int c = nt * 8 + 2 * tg;
        *(float2*)(Og + (size_t)g * DMODEL + c) =
            make_float2(oacc[nt][0] * inv0, oacc[nt][1] * inv0);
        *(float2*)(Og + (size_t)(g + 8) * DMODEL + c) =
            make_float2(oacc[nt][2] * inv1, oacc[nt][3] * inv1);
    }
}

// ---------------------------------------------------------------------------
// Launch
// ---------------------------------------------------------------------------
extern "C" void kernel_launch(void* const* d_in, const int* in_sizes, int n_in,
                              void* d_out, int out_size)
{
    const float* x      = (const float*)d_in[0];
    const int*   mask   = (const int*)  d_in[1];
    const int*   causal = (const int*)  d_in[2];
    const float* Wq     = (const float*)d_in[3];
    const float* Wk     = (const float*)d_in[4];
    const float* Wv     = (const float*)d_in[5];
    const float* Wo     = (const float*)d_in[6];
    float*       out    = (float*)d_out;

    float *qp, *kp, *vp, *ap;
    cudaGetSymbolAddress((void**)&qp, g_Q);
    cudaGetSymbolAddress((void**)&kp, g_K);
    cudaGetSymbolAddress((void**)&vp, g_V);
    cudaGetSymbolAddress((void**)&ap, g_A);

    static bool attr_done = false;
    if (!attr_done) {
        cudaFuncSetAttribute(tf32gemm, cudaFuncAttributeMaxDynamicSharedMemorySize,
                             GEMM_SMEM_BYTES);
        cudaFuncSetAttribute(attn_mma, cudaFuncAttributeMaxDynamicSharedMemorySize,
                             ATTN_SMEM_BYTES);
        attr_done = true;
    }

    dim3 ggrid(DMODEL / BN, MROWS / BM);   // (8, 32)
    dim3 gblk(256);

    tf32gemm<<<ggrid, gblk, GEMM_SMEM_BYTES>>>(x, Wq, qp, MROWS, DMODEL, DMODEL);
    tf32gemm<<<ggrid, gblk, GEMM_SMEM_BYTES>>>(x, Wk, kp, MROWS, DMODEL, DMODEL);
    tf32gemm<<<ggrid, gblk, GEMM_SMEM_BYTES>>>(x, Wv, vp, MROWS, DMODEL, DMODEL);

    dim3 agrid(SEQ / AQT, NHEAD, BATCH);   // (16, 16, 2)
    attn_mma<<<agrid, 256, ATTN_SMEM_BYTES>>>(qp, kp, vp, mask, causal, ap);

    tf32gemm<<<ggrid, gblk, GEMM_SMEM_BYTES>>>(ap, Wo, out, MROWS, DMODEL, DMODEL);
}

// round 12
// speedup vs baseline: 2.7418x; 1.3446x over previous
#include <cuda_runtime.h>
#include <cuda_bf16.h>
#include <math.h>
#include <stdint.h>

// ---------------------------------------------------------------------------
// Problem constants
// ---------------------------------------------------------------------------
#define BATCH   2
#define SEQ     2048
#define DMODEL  1024
#define NHEAD   16
#define HDIM    64
#define MROWS   (BATCH * SEQ)      // 4096

// ---------------------------------------------------------------------------
// Scratch
// ---------------------------------------------------------------------------
__device__ float g_Q[MROWS * DMODEL];
__device__ float g_K[MROWS * DMODEL];
__device__ float g_V[MROWS * DMODEL];
__device__ float g_A[MROWS * DMODEL];

// ---------------------------------------------------------------------------
// Common helpers
// ---------------------------------------------------------------------------
__device__ __forceinline__ void cp_async16(void* smem_dst, const void* gsrc) {
    uint32_t d = (uint32_t)__cvta_generic_to_shared(smem_dst);
    asm volatile("cp.async.cg.shared.global [%0], [%1], 16;\n" :: "r"(d), "l"(gsrc));
}

// ---- bf16 hi/lo helpers -----------------------------------------------------
// pack2(e0,e1): e0 -> lower half, e1 -> upper half (first PTX source = upper)
__device__ __forceinline__ uint32_t pack_bf16(float e0, float e1) {
    uint32_t r;
    asm("cvt.rn.bf16x2.f32 %0, %1, %2;\n" : "=r"(r) : "f"(e1), "f"(e0));
    return r;
}
__device__ __forceinline__ float bf16_lo_f(uint32_t w) { return __uint_as_float(w << 16); }
__device__ __forceinline__ float bf16_hi_f(uint32_t w) { return __uint_as_float(w & 0xffff0000u); }
// split pair (e0,e1) into packed hi word + packed lo-residual word
__device__ __forceinline__ void bf16x3_split(float e0, float e1, uint32_t& hi, uint32_t& lo) {
    hi = pack_bf16(e0, e1);
    float r0 = e0 - bf16_lo_f(hi);
    float r1 = e1 - bf16_hi_f(hi);
    lo = pack_bf16(r0, r1);
}

#define MMA_BF16(ACC, A0, A1, A2, A3, B0, B1)                               \
    asm volatile(                                                           \
        "mma.sync.aligned.m16n8k16.row.col.f32.bf16.bf16.f32 "              \
        "{%0,%1,%2,%3}, {%4,%5,%6,%7}, {%8,%9}, {%0,%1,%2,%3};\n"           \
        : "+f"(ACC[0]), "+f"(ACC[1]), "+f"(ACC[2]), "+f"(ACC[3])            \
        : "r"(A0), "r"(A1), "r"(A2), "r"(A3), "r"(B0), "r"(B1))

// ---------------------------------------------------------------------------
// bf16x3 GEMM: C[M,N] = A[M,K] * B[K,N], row-major fp32 in/out.
// cp.async double-buffered raw fp32 staging (validated); fragments packed to
// bf16 hi/lo in registers; m16n8k16 MMAs, 3 passes (lo*hi + hi*lo + hi*hi).
// 128x128x32 tile, 256 threads (8 warps as 2x4), warp tile 64x32.
// ---------------------------------------------------------------------------
#define BM 128
#define BN 128
#define BK 32
#define ASTR 36
#define BSTR 136
#define ABUF (BM * ASTR)
#define BBUF (BK * BSTR)
#define GEMM_SMEM_BYTES ((2 * ABUF + 2 * BBUF) * 4)

__global__ __launch_bounds__(256)
void bf16gemm(const float* __restrict__ A, const float* __restrict__ Bw,
              float* __restrict__ C, int M, int N, int K)
{
    extern __shared__ float sm[];
    float* As = sm;
    float* Bs = sm + 2 * ABUF;

    const int tid  = threadIdx.x;
    const int lane = tid & 31;
    const int wid  = tid >> 5;
    const int g    = lane >> 2;
    const int tg   = lane & 3;
    const int warp_m = wid >> 2;
    const int warp_n = wid & 3;

    const int bM = blockIdx.y * BM;
    const int bN = blockIdx.x * BN;

    const float* Ag = A + (size_t)bM * K;
    const float* Bg = Bw + bN;

    float acc[4][4][4];
    #pragma unroll
    for (int i = 0; i < 4; ++i)
        #pragma unroll
        for (int j = 0; j < 4; ++j)
            #pragma unroll
            for (int c = 0; c < 4; ++c) acc[i][j][c] = 0.f;

    const int NK = K / BK;

    {
        #pragma unroll
        for (int j = 0; j < 4; ++j) {
            int idx = tid + j * 256;
            int r = idx >> 3, q = idx & 7;
            cp_async16(&As[r * ASTR + q * 4], Ag + (size_t)r * K + q * 4);
        }
        #pragma unroll
        for (int j = 0; j < 4; ++j) {
            int idx = tid + j * 256;
            int r = idx >> 5, q = idx & 31;
            cp_async16(&Bs[r * BSTR + q * 4], Bg + (size_t)r * N + q * 4);
        }
        asm volatile("cp.async.commit_group;\n");
    }

    int buf = 0;
    for (int kt = 0; kt < NK; ++kt) {
        asm volatile("cp.async.wait_group 0;\n");
        __syncthreads();

        if (kt + 1 < NK) {
            const int k0 = (kt + 1) * BK;
            const int ob = buf ^ 1;
            #pragma unroll
            for (int j = 0; j < 4; ++j) {
                int idx = tid + j * 256;
                int r = idx >> 3, q = idx & 7;
                cp_async16(&As[ob * ABUF + r * ASTR + q * 4],
                           Ag + (size_t)r * K + k0 + q * 4);
            }
            #pragma unroll
            for (int j = 0; j < 4; ++j) {
                int idx = tid + j * 256;
                int r = idx >> 5, q = idx & 31;
                cp_async16(&Bs[ob * BBUF + r * BSTR + q * 4],
                           Bg + (size_t)(k0 + r) * N + q * 4);
            }
            asm volatile("cp.async.commit_group;\n");
        }

        // ---- compute on buf: 2 x k16 chunks over BK=32 ----
        const float* Ab = &As[buf * ABUF + (warp_m * 64) * ASTR];
        const float* Bb = &Bs[buf * BBUF + warp_n * 32];
        #pragma unroll
        for (int ks = 0; ks < 2; ++ks) {
            const int kc = ks * 16;
            uint32_t ah[4][4], al[4][4], bh[4][2], bl[4][2];
            #pragma unroll
            for (int mt = 0; mt < 4; ++mt) {
                const float* p0 = Ab + (mt * 16 + g) * ASTR + kc + 2 * tg;
                const float* p1 = p0 + 8 * ASTR;
                float2 x0 = *(const float2*)p0;        // row g,   k 2tg..2tg+1
                float2 x1 = *(const float2*)p1;        // row g+8
                float2 x2 = *(const float2*)(p0 + 8);  // row g,   k 8+2tg..
                float2 x3 = *(const float2*)(p1 + 8);  // row g+8
                bf16x3_split(x0.x, x0.y, ah[mt][0], al[mt][0]);
                bf16x3_split(x1.x, x1.y, ah[mt][1], al[mt][1]);
                bf16x3_split(x2.x, x2.y, ah[mt][2], al[mt][2]);
                bf16x3_split(x3.x, x3.y, ah[mt][3], al[mt][3]);
            }
            #pragma unroll
            for (int nt = 0; nt < 4; ++nt) {
                const int n = nt * 8 + g;
                const float* pk = Bb + (kc + 2 * tg) * BSTR + n;
                bf16x3_split(pk[0],         pk[BSTR],     bh[nt][0], bl[nt][0]);
                bf16x3_split(pk[8 * BSTR],  pk[9 * BSTR], bh[nt][1], bl[nt][1]);
            }
            #pragma unroll
            for (int mt = 0; mt < 4; ++mt)
                #pragma unroll
                for (int nt = 0; nt < 4; ++nt) {
                    MMA_BF16(acc[mt][nt], al[mt][0], al[mt][1], al[mt][2], al[mt][3],
                             bh[nt][0], bh[nt][1]);
                    MMA_BF16(acc[mt][nt], ah[mt][0], ah[mt][1], ah[mt][2], ah[mt][3],
                             bl[nt][0], bl[nt][1]);
                    MMA_BF16(acc[mt][nt], ah[mt][0], ah[mt][1], ah[mt][2], ah[mt][3],
                             bh[nt][0], bh[nt][1]);
                }
        }
        __syncthreads();
        buf ^= 1;
    }

    float* Cb = C + (size_t)(bM + warp_m * 64) * N + bN + warp_n * 32;
    #pragma unroll
    for (int mt = 0; mt < 4; ++mt) {
        #pragma unroll
        for (int nt = 0; nt < 4; ++nt) {
            float* p0 = Cb + (size_t)(mt * 16 + g) * N + nt * 8 + 2 * tg;
            float* p1 = Cb + (size_t)(mt * 16 + g + 8) * N + nt * 8 + 2 * tg;
            *(float2*)p0 = make_float2(acc[mt][nt][0], acc[mt][nt][1]);
            *(float2*)p1 = make_float2(acc[mt][nt][2], acc[mt][nt][3]);
        }
    }
}

// ---------------------------------------------------------------------------
// bf16x3 tensor-core flash attention (m16n8k16) — unchanged from round 11
// (passing, attn=270us, rel_err 2.6e-5).
// ---------------------------------------------------------------------------
#define AQT  128
#define AKT  64
#define QSTRW 36
#define KSTRW 36
#define VSTRW 72

#define SM_QH   0
#define SM_QL   (SM_QH + 128 * QSTRW)
#define SM_KH   (SM_QL + 128 * QSTRW)
#define SM_KL   (SM_KH + 64 * KSTRW)
#define SM_VH   (SM_KL + 64 * KSTRW)
#define SM_VL   (SM_VH + 32 * VSTRW)
#define SM_MSK  (SM_VL + 32 * VSTRW)
#define ATTN_SMEM_BYTES ((SM_MSK + 64 + 16) * 4)   // 74,048 bytes

__global__ __launch_bounds__(256, 2)
void attn_mma(const float* __restrict__ Q, const float* __restrict__ K,
              const float* __restrict__ V, const int* __restrict__ mask,
              const int* __restrict__ causal_p, float* __restrict__ O)
{
    extern __shared__ uint32_t smw[];
    uint32_t* sQh = smw + SM_QH;
    uint32_t* sQl = smw + SM_QL;
    uint32_t* sKh = smw + SM_KH;
    uint32_t* sKl = smw + SM_KL;
    uint32_t* sVh = smw + SM_VH;
    uint32_t* sVl = smw + SM_VL;
    int*      sM  = (int*)(smw + SM_MSK);

    const int b   = blockIdx.z;
    const int h   = blockIdx.y;
    const int qt  = blockIdx.x;
    const int tid = threadIdx.x;
    const int lane = tid & 31;
    const int wid  = tid >> 5;
    const int g    = lane >> 2;
    const int tg   = lane & 3;
    const int m0   = wid * 16;
    const int causal = *causal_p;

    const float* Qg = Q + ((size_t)(b * SEQ + qt * AQT)) * DMODEL + h * HDIM;
    #pragma unroll
    for (int j = 0; j < 8; ++j) {
        int idx = tid + j * 256;
        int r = idx >> 4, cq = idx & 15;
        float4 qv = *(const float4*)(Qg + (size_t)r * DMODEL + cq * 4);
        uint32_t h0, l0, h1, l1;
        bf16x3_split(qv.x, qv.y, h0, l0);
        bf16x3_split(qv.z, qv.w, h1, l1);
        sQh[r * QSTRW + cq * 2]     = h0;
        sQh[r * QSTRW + cq * 2 + 1] = h1;
        sQl[r * QSTRW + cq * 2]     = l0;
        sQl[r * QSTRW + cq * 2 + 1] = l1;
    }

    float oacc[8][4];
    #pragma unroll
    for (int nt = 0; nt < 8; ++nt)
        #pragma unroll
        for (int c = 0; c < 4; ++c) oacc[nt][c] = 0.f;
    float mrun0 = -1e30f, mrun1 = -1e30f, l0s = 0.f, l1s = 0.f;

    const int ntiles = causal ? ((qt + 1) * (AQT / AKT)) : (SEQ / AKT);
    const float* Kg = K + ((size_t)(b * SEQ)) * DMODEL + h * HDIM;
    const float* Vg = V + ((size_t)(b * SEQ)) * DMODEL + h * HDIM;

    for (int t = 0; t < ntiles; ++t) {
        const int kbase = t * AKT;
        __syncthreads();

        #pragma unroll
        for (int j = 0; j < 4; ++j) {
            int idx = tid + j * 256;
            int r = idx >> 4, cq = idx & 15;
            float4 kv = *(const float4*)(Kg + (size_t)(kbase + r) * DMODEL + cq * 4);
            uint32_t h0, lo0, h1, lo1;
            bf16x3_split(kv.x, kv.y, h0, lo0);
            bf16x3_split(kv.z, kv.w, h1, lo1);
            sKh[r * KSTRW + cq * 2]     = h0;
            sKh[r * KSTRW + cq * 2 + 1] = h1;
            sKl[r * KSTRW + cq * 2]     = lo0;
            sKl[r * KSTRW + cq * 2 + 1] = lo1;
        }
        #pragma unroll
        for (int j = 0; j < 2; ++j) {
            int idx = tid + j * 256;
            int kp = idx >> 4, cq = idx & 15;
            const float* v0 = Vg + (size_t)(kbase + 2 * kp) * DMODEL + cq * 4;
            float4 a = *(const float4*)v0;
            float4 bb = *(const float4*)(v0 + DMODEL);
            uint32_t hh, ll;
            bf16x3_split(a.x, bb.x, hh, ll);
            sVh[kp * VSTRW + cq * 4 + 0] = hh; sVl[kp * VSTRW + cq * 4 + 0] = ll;
            bf16x3_split(a.y, bb.y, hh, ll);
            sVh[kp * VSTRW + cq * 4 + 1] = hh; sVl[kp * VSTRW + cq * 4 + 1] = ll;
            bf16x3_split(a.z, bb.z, hh, ll);
            sVh[kp * VSTRW + cq * 4 + 2] = hh; sVl[kp * VSTRW + cq * 4 + 2] = ll;
            bf16x3_split(a.w, bb.w, hh, ll);
            sVh[kp * VSTRW + cq * 4 + 3] = hh; sVl[kp * VSTRW + cq * 4 + 3] = ll;
        }
        if (tid < AKT) sM[tid] = mask[b * SEQ + kbase + tid];
        __syncthreads();

        float sacc[8][4];
        #pragma unroll
        for (int nt = 0; nt < 8; ++nt)
            #pragma unroll
            for (int c = 0; c < 4; ++c) sacc[nt][c] = 0.f;

        #pragma unroll
        for (int kt = 0; kt < 4; ++kt) {
            const int kw = 8 * kt + tg;
            uint32_t qh0 = sQh[(m0 + g) * QSTRW + kw];
            uint32_t qh1 = sQh[(m0 + g + 8) * QSTRW + kw];
            uint32_t qh2 = sQh[(m0 + g) * QSTRW + kw + 4];
            uint32_t qh3 = sQh[(m0 + g + 8) * QSTRW + kw + 4];
            uint32_t ql0 = sQl[(m0 + g) * QSTRW + kw];
            uint32_t ql1 = sQl[(m0 + g + 8) * QSTRW + kw];
            uint32_t ql2 = sQl[(m0 + g) * QSTRW + kw + 4];
            uint32_t ql3 = sQl[(m0 + g + 8) * QSTRW + kw + 4];
            #pragma unroll
            for (int nt = 0; nt < 8; ++nt) {
                const int ka = (nt * 8 + g) * KSTRW + kw;
                uint32_t bh0 = sKh[ka], bh1 = sKh[ka + 4];
                uint32_t bl0 = sKl[ka], bl1 = sKl[ka + 4];
                MMA_BF16(sacc[nt], ql0, ql1, ql2, ql3, bh0, bh1);
                MMA_BF16(sacc[nt], qh0, qh1, qh2, qh3, bl0, bl1);
                MMA_BF16(sacc[nt], qh0, qh1, qh2, qh3, bh0, bh1);
            }
        }

        const int row0 = qt * AQT + m0 + g;
        const int row1 = row0 + 8;
        const bool diag = causal && (kbase + AKT - 1 > qt * AQT + m0);
        float rmax0 = -1e30f, rmax1 = -1e30f;
        #pragma unroll
        for (int nt = 0; nt < 8; ++nt) {
            const int c0 = nt * 8 + 2 * tg;
            const int c1 = c0 + 1;
            const bool k0ok = sM[c0] != 0;
            const bool k1ok = sM[c1] != 0;
            const int gc0 = kbase + c0, gc1 = kbase + c1;
            bool v00 = k0ok && (!diag || gc0 <= row0);
            bool v01 = k1ok && (!diag || gc1 <= row0);
            bool v10 = k0ok && (!diag || gc0 <= row1);
            bool v11 = k1ok && (!diag || gc1 <= row1);
            sacc[nt][0] = v00 ? sacc[nt][0] * 0.125f : -1e30f;
            sacc[nt][1] = v01 ? sacc[nt][1] * 0.125f : -1e30f;
            sacc[nt][2] = v10 ? sacc[nt][2] * 0.125f : -1e30f;
            sacc[nt][3] = v11 ? sacc[nt][3] * 0.125f : -1e30f;
            rmax0 = fmaxf(rmax0, fmaxf(sacc[nt][0], sacc[nt][1]));
            rmax1 = fmaxf(rmax1, fmaxf(sacc[nt][2], sacc[nt][3]));
        }
        rmax0 = fmaxf(rmax0, __shfl_xor_sync(0xffffffffu, rmax0, 1));
        rmax0 = fmaxf(rmax0, __shfl_xor_sync(0xffffffffu, rmax0, 2));
        rmax1 = fmaxf(rmax1, __shfl_xor_sync(0xffffffffu, rmax1, 1));
        rmax1 = fmaxf(rmax1, __shfl_xor_sync(0xffffffffu, rmax1, 2));

        const float mnew0 = fmaxf(mrun0, rmax0);
        const float mnew1 = fmaxf(mrun1, rmax1);
        const float al0 = __expf(mrun0 - mnew0);
        const float al1 = __expf(mrun1 - mnew1);
        mrun0 = mnew0; mrun1 = mnew1;

        float rsum0 = 0.f, rsum1 = 0.f;
        #pragma unroll
        for (int nt = 0; nt < 8; ++nt) {
            sacc[nt][0] = __expf(sacc[nt][0] - mnew0);
            sacc[nt][1] = __expf(sacc[nt][1] - mnew0);
            sacc[nt][2] = __expf(sacc[nt][2] - mnew1);
            sacc[nt][3] = __expf(sacc[nt][3] - mnew1);
            rsum0 += sacc[nt][0] + sacc[nt][1];
            rsum1 += sacc[nt][2] + sacc[nt][3];
        }
        rsum0 += __shfl_xor_sync(0xffffffffu, rsum0, 1);
        rsum0 += __shfl_xor_sync(0xffffffffu, rsum0, 2);
        rsum1 += __shfl_xor_sync(0xffffffffu, rsum1, 1);
        rsum1 += __shfl_xor_sync(0xffffffffu, rsum1, 2);
        l0s = l0s * al0 + rsum0;
        l1s = l1s * al1 + rsum1;

        #pragma unroll
        for (int nt = 0; nt < 8; ++nt) {
            oacc[nt][0] *= al0; oacc[nt][1] *= al0;
            oacc[nt][2] *= al1; oacc[nt][3] *= al1;
        }

        #pragma unroll
        for (int kt = 0; kt < 4; ++kt) {
            uint32_t ph0, pl0, ph1, pl1, ph2, pl2, ph3, pl3;
            bf16x3_split(sacc[2 * kt][0],     sacc[2 * kt][1],     ph0, pl0);
            bf16x3_split(sacc[2 * kt][2],     sacc[2 * kt][3],     ph1, pl1);
            bf16x3_split(sacc[2 * kt + 1][0], sacc[2 * kt + 1][1], ph2, pl2);
            bf16x3_split(sacc[2 * kt + 1][2], sacc[2 * kt + 1][3], ph3, pl3);
            #pragma unroll
            for (int nt = 0; nt < 8; ++nt) {
                const int va = (8 * kt + tg) * VSTRW + nt * 8 + g;
                uint32_t bh0 = sVh[va], bh1 = sVh[va + 4 * VSTRW];
                uint32_t bl0 = sVl[va], bl1 = sVl[va + 4 * VSTRW];
                MMA_BF16(oacc[nt], pl0, pl1, pl2, pl3, bh0, bh1);
                MMA_BF16(oacc[nt], ph0, ph1, ph2, ph3, bl0, bl1);
                MMA_BF16(oacc[nt], ph0, ph1, ph2, ph3, bh0, bh1);
            }
        }
    }

    const float inv0 = 1.f / l0s;
    const float inv1 = 1.f / l1s;
    float* Og = O + ((size_t)(b * SEQ + qt * AQT + m0)) * DMODEL + h * HDIM;
    #pragma unroll
    for (int nt = 0; nt < 8; ++nt) {
        const int c = nt * 8 + 2 * tg;
        *(float2*)(Og + (size_t)g * DMODEL + c) =
            make_float2(oacc[nt][0] * inv0, oacc[nt][1] * inv0);
        *(float2*)(Og + (size_t)(g + 8) * DMODEL + c) =
            make_float2(oacc[nt][2] * inv1, oacc[nt][3] * inv1);
    }
}

// ---------------------------------------------------------------------------
// Launch
// ---------------------------------------------------------------------------
extern "C" void kernel_launch(void* const* d_in, const int* in_sizes, int n_in,
                              void* d_out, int out_size)
{
    const float* x      = (const float*)d_in[0];
    const int*   mask   = (const int*)  d_in[1];
    const int*   causal = (const int*)  d_in[2];
    const float* Wq     = (const float*)d_in[3];
    const float* Wk     = (const float*)d_in[4];
    const float* Wv     = (const float*)d_in[5];
    const float* Wo     = (const float*)d_in[6];
    float*       out    = (float*)d_out;

    float *qp, *kp, *vp, *ap;
    cudaGetSymbolAddress((void**)&qp, g_Q);
    cudaGetSymbolAddress((void**)&kp, g_K);
    cudaGetSymbolAddress((void**)&vp, g_V);
    cudaGetSymbolAddress((void**)&ap, g_A);

    static bool attr_done = false;
    if (!attr_done) {
        cudaFuncSetAttribute(bf16gemm, cudaFuncAttributeMaxDynamicSharedMemorySize,
                             GEMM_SMEM_BYTES);
        cudaFuncSetAttribute(attn_mma, cudaFuncAttributeMaxDynamicSharedMemorySize,
                             ATTN_SMEM_BYTES);
        attr_done = true;
    }

    dim3 ggrid(DMODEL / BN, MROWS / BM);   // (8, 32)
    dim3 gblk(256);

    bf16gemm<<<ggrid, gblk, GEMM_SMEM_BYTES>>>(x, Wq, qp, MROWS, DMODEL, DMODEL);
    bf16gemm<<<ggrid, gblk, GEMM_SMEM_BYTES>>>(x, Wk, kp, MROWS, DMODEL, DMODEL);
    bf16gemm<<<ggrid, gblk, GEMM_SMEM_BYTES>>>(x, Wv, vp, MROWS, DMODEL, DMODEL);

    dim3 agrid(SEQ / AQT, NHEAD, BATCH);   // (16, 16, 2)
    attn_mma<<<agrid, 256, ATTN_SMEM_BYTES>>>(qp, kp, vp, mask, causal, ap);

    bf16gemm<<<ggrid, gblk, GEMM_SMEM_BYTES>>>(ap, Wo, out, MROWS, DMODEL, DMODEL);
}

// round 13
// speedup vs baseline: 2.9552x; 1.0778x over previous
#include <cuda_runtime.h>
#include <cuda_bf16.h>
#include <math.h>
#include <stdint.h>

// ---------------------------------------------------------------------------
// Problem constants
// ---------------------------------------------------------------------------
#define BATCH   2
#define SEQ     2048
#define DMODEL  1024
#define NHEAD   16
#define HDIM    64
#define MROWS   (BATCH * SEQ)      // 4096

// ---------------------------------------------------------------------------
// Scratch
// ---------------------------------------------------------------------------
__device__ float g_Q[MROWS * DMODEL];
__device__ float g_K[MROWS * DMODEL];
__device__ float g_V[MROWS * DMODEL];
__device__ float g_A[MROWS * DMODEL];

// ---------------------------------------------------------------------------
// Common helpers
// ---------------------------------------------------------------------------
__device__ __forceinline__ void cp_async16(void* smem_dst, const void* gsrc) {
    uint32_t d = (uint32_t)__cvta_generic_to_shared(smem_dst);
    asm volatile("cp.async.cg.shared.global [%0], [%1], 16;\n" :: "r"(d), "l"(gsrc));
}

// ---- bf16 hi/lo helpers -----------------------------------------------------
__device__ __forceinline__ uint32_t pack_bf16(float e0, float e1) {
    uint32_t r;
    asm("cvt.rn.bf16x2.f32 %0, %1, %2;\n" : "=r"(r) : "f"(e1), "f"(e0));
    return r;
}
__device__ __forceinline__ float bf16_lo_f(uint32_t w) { return __uint_as_float(w << 16); }
__device__ __forceinline__ float bf16_hi_f(uint32_t w) { return __uint_as_float(w & 0xffff0000u); }
__device__ __forceinline__ void bf16x3_split(float e0, float e1, uint32_t& hi, uint32_t& lo) {
    hi = pack_bf16(e0, e1);
    float r0 = e0 - bf16_lo_f(hi);
    float r1 = e1 - bf16_hi_f(hi);
    lo = pack_bf16(r0, r1);
}

#define MMA_BF16(ACC, A0, A1, A2, A3, B0, B1)                               \
    asm volatile(                                                           \
        "mma.sync.aligned.m16n8k16.row.col.f32.bf16.bf16.f32 "              \
        "{%0,%1,%2,%3}, {%4,%5,%6,%7}, {%8,%9}, {%0,%1,%2,%3};\n"           \
        : "+f"(ACC[0]), "+f"(ACC[1]), "+f"(ACC[2]), "+f"(ACC[3])            \
        : "r"(A0), "r"(A1), "r"(A2), "r"(A3), "r"(B0), "r"(B1))

// ---------------------------------------------------------------------------
// bf16x3 GEMM: C[M,N] = A[M,K] * B[K,N], row-major fp32 in/out.
// 128x128x32 tile, 256 threads, warp tile 64x32, m16n8k16 bf16 hi/lo x3.
// NOW 2 CTAs/SM (143.4KB smem / SM, regs capped at 128).
// ---------------------------------------------------------------------------
#define BM 128
#define BN 128
#define BK 32
#define ASTR 36
#define BSTR 136
#define ABUF (BM * ASTR)
#define BBUF (BK * BSTR)
#define GEMM_SMEM_BYTES ((2 * ABUF + 2 * BBUF) * 4)   // 71,680

__global__ __launch_bounds__(256, 2)
void bf16gemm(const float* __restrict__ A, const float* __restrict__ Bw,
              float* __restrict__ C, int M, int N, int K)
{
    extern __shared__ float sm[];
    float* As = sm;
    float* Bs = sm + 2 * ABUF;

    const int tid  = threadIdx.x;
    const int lane = tid & 31;
    const int wid  = tid >> 5;
    const int g    = lane >> 2;
    const int tg   = lane & 3;
    const int warp_m = wid >> 2;
    const int warp_n = wid & 3;

    const int bM = blockIdx.y * BM;
    const int bN = blockIdx.x * BN;

    const float* Ag = A + (size_t)bM * K;
    const float* Bg = Bw + bN;

    float acc[4][4][4];
    #pragma unroll
    for (int i = 0; i < 4; ++i)
        #pragma unroll
        for (int j = 0; j < 4; ++j)
            #pragma unroll
            for (int c = 0; c < 4; ++c) acc[i][j][c] = 0.f;

    const int NK = K / BK;

    {
        #pragma unroll
        for (int j = 0; j < 4; ++j) {
            int idx = tid + j * 256;
            int r = idx >> 3, q = idx & 7;
            cp_async16(&As[r * ASTR + q * 4], Ag + (size_t)r * K + q * 4);
        }
        #pragma unroll
        for (int j = 0; j < 4; ++j) {
            int idx = tid + j * 256;
            int r = idx >> 5, q = idx & 31;
            cp_async16(&Bs[r * BSTR + q * 4], Bg + (size_t)r * N + q * 4);
        }
        asm volatile("cp.async.commit_group;\n");
    }

    int buf = 0;
    for (int kt = 0; kt < NK; ++kt) {
        asm volatile("cp.async.wait_group 0;\n");
        __syncthreads();

        if (kt + 1 < NK) {
            const int k0 = (kt + 1) * BK;
            const int ob = buf ^ 1;
            #pragma unroll
            for (int j = 0; j < 4; ++j) {
                int idx = tid + j * 256;
                int r = idx >> 3, q = idx & 7;
                cp_async16(&As[ob * ABUF + r * ASTR + q * 4],
                           Ag + (size_t)r * K + k0 + q * 4);
            }
            #pragma unroll
            for (int j = 0; j < 4; ++j) {
                int idx = tid + j * 256;
                int r = idx >> 5, q = idx & 31;
                cp_async16(&Bs[ob * BBUF + r * BSTR + q * 4],
                           Bg + (size_t)(k0 + r) * N + q * 4);
            }
            asm volatile("cp.async.commit_group;\n");
        }

        // ---- compute on buf: 2 x k16 chunks over BK=32 ----
        const float* Ab = &As[buf * ABUF + (warp_m * 64) * ASTR];
        const float* Bb = &Bs[buf * BBUF + warp_n * 32];
        #pragma unroll
        for (int ks = 0; ks < 2; ++ks) {
            const int kc = ks * 16;
            uint32_t ah[4][4], al[4][4], bh[4][2], bl[4][2];
            #pragma unroll
            for (int mt = 0; mt < 4; ++mt) {
                const float* p0 = Ab + (mt * 16 + g) * ASTR + kc + 2 * tg;
                const float* p1 = p0 + 8 * ASTR;
                float2 x0 = *(const float2*)p0;
                float2 x1 = *(const float2*)p1;
                float2 x2 = *(const float2*)(p0 + 8);
                float2 x3 = *(const float2*)(p1 + 8);
                bf16x3_split(x0.x, x0.y, ah[mt][0], al[mt][0]);
                bf16x3_split(x1.x, x1.y, ah[mt][1], al[mt][1]);
                bf16x3_split(x2.x, x2.y, ah[mt][2], al[mt][2]);
                bf16x3_split(x3.x, x3.y, ah[mt][3], al[mt][3]);
            }
            #pragma unroll
            for (int nt = 0; nt < 4; ++nt) {
                const int n = nt * 8 + g;
                const float* pk = Bb + (kc + 2 * tg) * BSTR + n;
                bf16x3_split(pk[0],         pk[BSTR],     bh[nt][0], bl[nt][0]);
                bf16x3_split(pk[8 * BSTR],  pk[9 * BSTR], bh[nt][1], bl[nt][1]);
            }
            #pragma unroll
            for (int mt = 0; mt < 4; ++mt)
                #pragma unroll
                for (int nt = 0; nt < 4; ++nt) {
                    MMA_BF16(acc[mt][nt], al[mt][0], al[mt][1], al[mt][2], al[mt][3],
                             bh[nt][0], bh[nt][1]);
                    MMA_BF16(acc[mt][nt], ah[mt][0], ah[mt][1], ah[mt][2], ah[mt][3],
                             bl[nt][0], bl[nt][1]);
                    MMA_BF16(acc[mt][nt], ah[mt][0], ah[mt][1], ah[mt][2], ah[mt][3],
                             bh[nt][0], bh[nt][1]);
                }
        }
        __syncthreads();
        buf ^= 1;
    }

    float* Cb = C + (size_t)(bM + warp_m * 64) * N + bN + warp_n * 32;
    #pragma unroll
    for (int mt = 0; mt < 4; ++mt) {
        #pragma unroll
        for (int nt = 0; nt < 4; ++nt) {
            float* p0 = Cb + (size_t)(mt * 16 + g) * N + nt * 8 + 2 * tg;
            float* p1 = Cb + (size_t)(mt * 16 + g + 8) * N + nt * 8 + 2 * tg;
            *(float2*)p0 = make_float2(acc[mt][nt][0], acc[mt][nt][1]);
            *(float2*)p1 = make_float2(acc[mt][nt][2], acc[mt][nt][3]);
        }
    }
}

// ---------------------------------------------------------------------------
// bf16x3 tensor-core flash attention (m16n8k16) — unchanged (280us, 2.6e-5).
// ---------------------------------------------------------------------------
#define AQT  128
#define AKT  64
#define QSTRW 36
#define KSTRW 36
#define VSTRW 72

#define SM_QH   0
#define SM_QL   (SM_QH + 128 * QSTRW)
#define SM_KH   (SM_QL + 128 * QSTRW)
#define SM_KL   (SM_KH + 64 * KSTRW)
#define SM_VH   (SM_KL + 64 * KSTRW)
#define SM_VL   (SM_VH + 32 * VSTRW)
#define SM_MSK  (SM_VL + 32 * VSTRW)
#define ATTN_SMEM_BYTES ((SM_MSK + 64 + 16) * 4)   // 74,048 bytes

__global__ __launch_bounds__(256, 2)
void attn_mma(const float* __restrict__ Q, const float* __restrict__ K,
              const float* __restrict__ V, const int* __restrict__ mask,
              const int* __restrict__ causal_p, float* __restrict__ O)
{
    extern __shared__ uint32_t smw[];
    uint32_t* sQh = smw + SM_QH;
    uint32_t* sQl = smw + SM_QL;
    uint32_t* sKh = smw + SM_KH;
    uint32_t* sKl = smw + SM_KL;
    uint32_t* sVh = smw + SM_VH;
    uint32_t* sVl = smw + SM_VL;
    int*      sM  = (int*)(smw + SM_MSK);

    const int b   = blockIdx.z;
    const int h   = blockIdx.y;
    const int qt  = blockIdx.x;
    const int tid = threadIdx.x;
    const int lane = tid & 31;
    const int wid  = tid >> 5;
    const int g    = lane >> 2;
    const int tg   = lane & 3;
    const int m0   = wid * 16;
    const int causal = *causal_p;

    const float* Qg = Q + ((size_t)(b * SEQ + qt * AQT)) * DMODEL + h * HDIM;
    #pragma unroll
    for (int j = 0; j < 8; ++j) {
        int idx = tid + j * 256;
        int r = idx >> 4, cq = idx & 15;
        float4 qv = *(const float4*)(Qg + (size_t)r * DMODEL + cq * 4);
        uint32_t h0, l0, h1, l1;
        bf16x3_split(qv.x, qv.y, h0, l0);
        bf16x3_split(qv.z, qv.w, h1, l1);
        sQh[r * QSTRW + cq * 2]     = h0;
        sQh[r * QSTRW + cq * 2 + 1] = h1;
        sQl[r * QSTRW + cq * 2]     = l0;
        sQl[r * QSTRW + cq * 2 + 1] = l1;
    }

    float oacc[8][4];
    #pragma unroll
    for (int nt = 0; nt < 8; ++nt)
        #pragma unroll
        for (int c = 0; c < 4; ++c) oacc[nt][c] = 0.f;
    float mrun0 = -1e30f, mrun1 = -1e30f, l0s = 0.f, l1s = 0.f;

    const int ntiles = causal ? ((qt + 1) * (AQT / AKT)) : (SEQ / AKT);
    const float* Kg = K + ((size_t)(b * SEQ)) * DMODEL + h * HDIM;
    const float* Vg = V + ((size_t)(b * SEQ)) * DMODEL + h * HDIM;

    for (int t = 0; t < ntiles; ++t) {
        const int kbase = t * AKT;
        __syncthreads();

        #pragma unroll
        for (int j = 0; j < 4; ++j) {
            int idx = tid + j * 256;
            int r = idx >> 4, cq = idx & 15;
            float4 kv = *(const float4*)(Kg + (size_t)(kbase + r) * DMODEL + cq * 4);
            uint32_t h0, lo0, h1, lo1;
            bf16x3_split(kv.x, kv.y, h0, lo0);
            bf16x3_split(kv.z, kv.w, h1, lo1);
            sKh[r * KSTRW + cq * 2]     = h0;
            sKh[r * KSTRW + cq * 2 + 1] = h1;
            sKl[r * KSTRW + cq * 2]     = lo0;
            sKl[r * KSTRW + cq * 2 + 1] = lo1;
        }
        #pragma unroll
        for (int j = 0; j < 2; ++j) {
            int idx = tid + j * 256;
            int kp = idx >> 4, cq = idx & 15;
            const float* v0 = Vg + (size_t)(kbase + 2 * kp) * DMODEL + cq * 4;
            float4 a = *(const float4*)v0;
            float4 bb = *(const float4*)(v0 + DMODEL);
            uint32_t hh, ll;
            bf16x3_split(a.x, bb.x, hh, ll);
            sVh[kp * VSTRW + cq * 4 + 0] = hh; sVl[kp * VSTRW + cq * 4 + 0] = ll;
            bf16x3_split(a.y, bb.y, hh, ll);
            sVh[kp * VSTRW + cq * 4 + 1] = hh; sVl[kp * VSTRW + cq * 4 + 1] = ll;
            bf16x3_split(a.z, bb.z, hh, ll);
            sVh[kp * VSTRW + cq * 4 + 2] = hh; sVl[kp * VSTRW + cq * 4 + 2] = ll;
            bf16x3_split(a.w, bb.w, hh, ll);
            sVh[kp * VSTRW + cq * 4 + 3] = hh; sVl[kp * VSTRW + cq * 4 + 3] = ll;
        }
        if (tid < AKT) sM[tid] = mask[b * SEQ + kbase + tid];
        __syncthreads();

        float sacc[8][4];
        #pragma unroll
        for (int nt = 0; nt < 8; ++nt)
            #pragma unroll
            for (int c = 0; c < 4; ++c) sacc[nt][c] = 0.f;

        #pragma unroll
        for (int kt = 0; kt < 4; ++kt) {
            const int kw = 8 * kt + tg;
            uint32_t qh0 = sQh[(m0 + g) * QSTRW + kw];
            uint32_t qh1 = sQh[(m0 + g + 8) * QSTRW + kw];
            uint32_t qh2 = sQh[(m0 + g) * QSTRW + kw + 4];
            uint32_t qh3 = sQh[(m0 + g + 8) * QSTRW + kw + 4];
            uint32_t ql0 = sQl[(m0 + g) * QSTRW + kw];
            uint32_t ql1 = sQl[(m0 + g + 8) * QSTRW + kw];
            uint32_t ql2 = sQl[(m0 + g) * QSTRW + kw + 4];
            uint32_t ql3 = sQl[(m0 + g + 8) * QSTRW + kw + 4];
            #pragma unroll
            for (int nt = 0; nt < 8; ++nt) {
                const int ka = (nt * 8 + g) * KSTRW + kw;
                uint32_t bh0 = sKh[ka], bh1 = sKh[ka + 4];
                uint32_t bl0 = sKl[ka], bl1 = sKl[ka + 4];
                MMA_BF16(sacc[nt], ql0, ql1, ql2, ql3, bh0, bh1);
                MMA_BF16(sacc[nt], qh0, qh1, qh2, qh3, bl0, bl1);
                MMA_BF16(sacc[nt], qh0, qh1, qh2, qh3, bh0, bh1);
            }
        }

        const int row0 = qt * AQT + m0 + g;
        const int row1 = row0 + 8;
        const bool diag = causal && (kbase + AKT - 1 > qt * AQT + m0);
        float rmax0 = -1e30f, rmax1 = -1e30f;
        #pragma unroll
        for (int nt = 0; nt < 8; ++nt) {
            const int c0 = nt * 8 + 2 * tg;
            const int c1 = c0 + 1;
            const bool k0ok = sM[c0] != 0;
            const bool k1ok = sM[c1] != 0;
            const int gc0 = kbase + c0, gc1 = kbase + c1;
            bool v00 = k0ok && (!diag || gc0 <= row0);
            bool v01 = k1ok && (!diag || gc1 <= row0);
            bool v10 = k0ok && (!diag || gc0 <= row1);
            bool v11 = k1ok && (!diag || gc1 <= row1);
            sacc[nt][0] = v00 ? sacc[nt][0] * 0.125f : -1e30f;
            sacc[nt][1] = v01 ? sacc[nt][1] * 0.125f : -1e30f;
            sacc[nt][2] = v10 ? sacc[nt][2] * 0.125f : -1e30f;
            sacc[nt][3] = v11 ? sacc[nt][3] * 0.125f : -1e30f;
            rmax0 = fmaxf(rmax0, fmaxf(sacc[nt][0], sacc[nt][1]));
            rmax1 = fmaxf(rmax1, fmaxf(sacc[nt][2], sacc[nt][3]));
        }
        rmax0 = fmaxf(rmax0, __shfl_xor_sync(0xffffffffu, rmax0, 1));
        rmax0 = fmaxf(rmax0, __shfl_xor_sync(0xffffffffu, rmax0, 2));
        rmax1 = fmaxf(rmax1, __shfl_xor_sync(0xffffffffu, rmax1, 1));
        rmax1 = fmaxf(rmax1, __shfl_xor_sync(0xffffffffu, rmax1, 2));

        const float mnew0 = fmaxf(mrun0, rmax0);
        const float mnew1 = fmaxf(mrun1, rmax1);
        const float al0 = __expf(mrun0 - mnew0);
        const float al1 = __expf(mrun1 - mnew1);
        mrun0 = mnew0; mrun1 = mnew1;

        float rsum0 = 0.f, rsum1 = 0.f;
        #pragma unroll
        for (int nt = 0; nt < 8; ++nt) {
            sacc[nt][0] = __expf(sacc[nt][0] - mnew0);
            sacc[nt][1] = __expf(sacc[nt][1] - mnew0);
            sacc[nt][2] = __expf(sacc[nt][2] - mnew1);
            sacc[nt][3] = __expf(sacc[nt][3] - mnew1);
            rsum0 += sacc[nt][0] + sacc[nt][1];
            rsum1 += sacc[nt][2] + sacc[nt][3];
        }
        rsum0 += __shfl_xor_sync(0xffffffffu, rsum0, 1);
        rsum0 += __shfl_xor_sync(0xffffffffu, rsum0, 2);
        rsum1 += __shfl_xor_sync(0xffffffffu, rsum1, 1);
        rsum1 += __shfl_xor_sync(0xffffffffu, rsum1, 2);
        l0s = l0s * al0 + rsum0;
        l1s = l1s * al1 + rsum1;

        #pragma unroll
        for (int nt = 0; nt < 8; ++nt) {
            oacc[nt][0] *= al0; oacc[nt][1] *= al0;
            oacc[nt][2] *= al1; oacc[nt][3] *= al1;
        }

        #pragma unroll
        for (int kt = 0; kt < 4; ++kt) {
            uint32_t ph0, pl0, ph1, pl1, ph2, pl2, ph3, pl3;
            bf16x3_split(sacc[2 * kt][0],     sacc[2 * kt][1],     ph0, pl0);
            bf16x3_split(sacc[2 * kt][2],     sacc[2 * kt][3],     ph1, pl1);
            bf16x3_split(sacc[2 * kt + 1][0], sacc[2 * kt + 1][1], ph2, pl2);
            bf16x3_split(sacc[2 * kt + 1][2], sacc[2 * kt + 1][3], ph3, pl3);
            #pragma unroll
            for (int nt = 0; nt < 8; ++nt) {
                const int va = (8 * kt + tg) * VSTRW + nt * 8 + g;
                uint32_t bh0 = sVh[va], bh1 = sVh[va + 4 * VSTRW];
                uint32_t bl0 = sVl[va], bl1 = sVl[va + 4 * VSTRW];
                MMA_BF16(oacc[nt], pl0, pl1, pl2, pl3, bh0, bh1);
                MMA_BF16(oacc[nt], ph0, ph1, ph2, ph3, bl0, bl1);
                MMA_BF16(oacc[nt], ph0, ph1, ph2, ph3, bh0, bh1);
            }
        }
    }

    const float inv0 = 1.f / l0s;
    const float inv1 = 1.f / l1s;
    float* Og = O + ((size_t)(b * SEQ + qt * AQT + m0)) * DMODEL + h * HDIM;
    #pragma unroll
    for (int nt = 0; nt < 8; ++nt) {
        const int c = nt * 8 + 2 * tg;
        *(float2*)(Og + (size_t)g * DMODEL + c) =
            make_float2(oacc[nt][0] * inv0, oacc[nt][1] * inv0);
        *(float2*)(Og + (size_t)(g + 8) * DMODEL + c) =
            make_float2(oacc[nt][2] * inv1, oacc[nt][3] * inv1);
    }
}

// ---------------------------------------------------------------------------
// Launch
// ---------------------------------------------------------------------------
extern "C" void kernel_launch(void* const* d_in, const int* in_sizes, int n_in,
                              void* d_out, int out_size)
{
    const float* x      = (const float*)d_in[0];
    const int*   mask   = (const int*)  d_in[1];
    const int*   causal = (const int*)  d_in[2];
    const float* Wq     = (const float*)d_in[3];
    const float* Wk     = (const float*)d_in[4];
    const float* Wv     = (const float*)d_in[5];
    const float* Wo     = (const float*)d_in[6];
    float*       out    = (float*)d_out;

    float *qp, *kp, *vp, *ap;
    cudaGetSymbolAddress((void**)&qp, g_Q);
    cudaGetSymbolAddress((void**)&kp, g_K);
    cudaGetSymbolAddress((void**)&vp, g_V);
    cudaGetSymbolAddress((void**)&ap, g_A);

    static bool attr_done = false;
    if (!attr_done) {
        cudaFuncSetAttribute(bf16gemm, cudaFuncAttributeMaxDynamicSharedMemorySize,
                             GEMM_SMEM_BYTES);
        cudaFuncSetAttribute(attn_mma, cudaFuncAttributeMaxDynamicSharedMemorySize,
                             ATTN_SMEM_BYTES);
        attr_done = true;
    }

    dim3 ggrid(DMODEL / BN, MROWS / BM);   // (8, 32)
    dim3 gblk(256);

    bf16gemm<<<ggrid, gblk, GEMM_SMEM_BYTES>>>(x, Wq, qp, MROWS, DMODEL, DMODEL);
    bf16gemm<<<ggrid, gblk, GEMM_SMEM_BYTES>>>(x, Wk, kp, MROWS, DMODEL, DMODEL);
    bf16gemm<<<ggrid, gblk, GEMM_SMEM_BYTES>>>(x, Wv, vp, MROWS, DMODEL, DMODEL);

    dim3 agrid(SEQ / AQT, NHEAD, BATCH);   // (16, 16, 2)
    attn_mma<<<agrid, 256, ATTN_SMEM_BYTES>>>(qp, kp, vp, mask, causal, ap);

    bf16gemm<<<ggrid, gblk, GEMM_SMEM_BYTES>>>(ap, Wo, out, MROWS, DMODEL, DMODEL);
}

// round 16
// speedup vs baseline: 2.9650x; 1.0033x over previous
#include <cuda_runtime.h>
#include <cuda_bf16.h>
#include <math.h>
#include <stdint.h>

// ---------------------------------------------------------------------------
// Problem constants
// ---------------------------------------------------------------------------
#define BATCH   2
#define SEQ     2048
#define DMODEL  1024
#define NHEAD   16
#define HDIM    64
#define MROWS   (BATCH * SEQ)      // 4096

// ---------------------------------------------------------------------------
// Scratch
// ---------------------------------------------------------------------------
__device__ float g_Q[MROWS * DMODEL];
__device__ float g_K[MROWS * DMODEL];
__device__ float g_V[MROWS * DMODEL];
__device__ float g_A[MROWS * DMODEL];

// ---------------------------------------------------------------------------
// bf16 hi/lo helpers
// ---------------------------------------------------------------------------
__device__ __forceinline__ uint32_t pack_bf16(float e0, float e1) {
    uint32_t r;
    asm("cvt.rn.bf16x2.f32 %0, %1, %2;\n" : "=r"(r) : "f"(e1), "f"(e0));
    return r;
}
__device__ __forceinline__ float bf16_lo_f(uint32_t w) { return __uint_as_float(w << 16); }
__device__ __forceinline__ float bf16_hi_f(uint32_t w) { return __uint_as_float(w & 0xffff0000u); }
__device__ __forceinline__ void bf16x3_split(float e0, float e1, uint32_t& hi, uint32_t& lo) {
    hi = pack_bf16(e0, e1);
    float r0 = e0 - bf16_lo_f(hi);
    float r1 = e1 - bf16_hi_f(hi);
    lo = pack_bf16(r0, r1);
}

#define MMA_BF16(ACC, A0, A1, A2, A3, B0, B1)                               \
    asm volatile(                                                           \
        "mma.sync.aligned.m16n8k16.row.col.f32.bf16.bf16.f32 "              \
        "{%0,%1,%2,%3}, {%4,%5,%6,%7}, {%8,%9}, {%0,%1,%2,%3};\n"           \
        : "+f"(ACC[0]), "+f"(ACC[1]), "+f"(ACC[2]), "+f"(ACC[3])            \
        : "r"(A0), "r"(A1), "r"(A2), "r"(A3), "r"(B0), "r"(B1))

// ---------------------------------------------------------------------------
// bf16x3 GEMM, attention-style staging: A/B split ONCE per tile into packed
// bf16 hi/lo smem; double-buffered with register prefetch of the next tile.
// C[M,N] = A[M,K]*B[K,N], fp32 in/out. 128x128x32 tile, 256 thr, 2 CTA/SM.
// ---------------------------------------------------------------------------
#define BM 128
#define BN 128
#define BK 32
#define ASTRW 20            // words/row: 16 + 4 pad -> frag banks (20g+tg)%32 distinct
#define BSTRW 136           // words/k-pair row: 128 + 8 pad -> (8tg+g)%32 distinct
#define AWRD  (BM * ASTRW)          // 2560 words per A plane
#define BWRD  ((BK / 2) * BSTRW)    // 2176 words per B plane
#define STG   (2 * AWRD + 2 * BWRD) // 9472 words per stage (Ah,Al,Bh,Bl)
#define GEMM_SMEM_BYTES (2 * STG * 4)   // 75,776 bytes

__global__ __launch_bounds__(256, 2)
void bf16gemm(const float* __restrict__ A, const float* __restrict__ Bw,
              float* __restrict__ C, int M, int N, int K)
{
    extern __shared__ uint32_t smw[];

    const int tid  = threadIdx.x;
    const int lane = tid & 31;
    const int wid  = tid >> 5;
    const int g    = lane >> 2;
    const int tg   = lane & 3;
    const int warp_m = wid >> 2;
    const int warp_n = wid & 3;

    const int bM = blockIdx.y * BM;
    const int bN = blockIdx.x * BN;

    const float* Ag = A + (size_t)bM * K;
    const float* Bg = Bw + bN;

    // per-thread staging coordinates
    const int ar = tid >> 3;            // A row for j-th chunk: ar + j*32
    const int aq = tid & 7;             // A col quad (0..7) -> k 4aq..4aq+3
    const int bkp = tid >> 5;           // B k-pair row for j-th chunk: bkp + j*8
    const int bnq = tid & 31;           // B col quad (0..31) -> n 4bnq..4bnq+3

    float acc[4][4][4];
    #pragma unroll
    for (int i = 0; i < 4; ++i)
        #pragma unroll
        for (int j = 0; j < 4; ++j)
            #pragma unroll
            for (int c = 0; c < 4; ++c) acc[i][j][c] = 0.f;

    const int NK = K / BK;

    // register prefetch buffers (tile t+1 while computing tile t)
    float4 aR[4];       // A: rows ar, ar+32, ar+64, ar+96 ; k quad aq
    float4 bR[2][2];    // B: k-pairs (bkp, bkp+8) x rows (2kp, 2kp+1) ; n quad bnq

    // ---- prologue: LDG tile 0 ----
    #pragma unroll
    for (int j = 0; j < 4; ++j)
        aR[j] = *(const float4*)(Ag + (size_t)(ar + j * 32) * K + aq * 4);
    #pragma unroll
    for (int j = 0; j < 2; ++j) {
        const float* p = Bg + (size_t)(2 * (bkp + j * 8)) * N + bnq * 4;
        bR[j][0] = *(const float4*)p;
        bR[j][1] = *(const float4*)(p + N);
    }

    int buf = 0;
    for (int kt = 0; kt < NK; ++kt) {
        uint32_t* Ah = smw + buf * STG;
        uint32_t* Al = Ah + AWRD;
        uint32_t* Bh = Al + AWRD;
        uint32_t* Bl = Bh + BWRD;

        // ---- split + store current regs into buf (plain vector STS) ----
        #pragma unroll
        for (int j = 0; j < 4; ++j) {
            uint32_t h0, l0, h1, l1;
            bf16x3_split(aR[j].x, aR[j].y, h0, l0);
            bf16x3_split(aR[j].z, aR[j].w, h1, l1);
            const int off = (ar + j * 32) * ASTRW + 2 * aq;   // even word -> 8B aligned
            *(uint2*)(Ah + off) = make_uint2(h0, h1);
            *(uint2*)(Al + off) = make_uint2(l0, l1);
        }
        #pragma unroll
        for (int j = 0; j < 2; ++j) {
            uint32_t h0, l0, h1, l1, h2, l2, h3, l3;
            bf16x3_split(bR[j][0].x, bR[j][1].x, h0, l0);
            bf16x3_split(bR[j][0].y, bR[j][1].y, h1, l1);
            bf16x3_split(bR[j][0].z, bR[j][1].z, h2, l2);
            bf16x3_split(bR[j][0].w, bR[j][1].w, h3, l3);
            const int off = (bkp + j * 8) * BSTRW + bnq * 4;  // mult of 4 words -> 16B aligned
            *(uint4*)(Bh + off) = make_uint4(h0, h1, h2, h3);
            *(uint4*)(Bl + off) = make_uint4(l0, l1, l2, l3);
        }

        // ---- LDG next tile into regs (overlaps with compute below) ----
        if (kt + 1 < NK) {
            const int k0 = (kt + 1) * BK;
            #pragma unroll
            for (int j = 0; j < 4; ++j)
                aR[j] = *(const float4*)(Ag + (size_t)(ar + j * 32) * K + k0 + aq * 4);
            #pragma unroll
            for (int j = 0; j < 2; ++j) {
                const float* p = Bg + (size_t)(k0 + 2 * (bkp + j * 8)) * N + bnq * 4;
                bR[j][0] = *(const float4*)p;
                bR[j][1] = *(const float4*)(p + N);
            }
        }

        __syncthreads();

        // ---- compute on buf: 2 x k16 chunks ----
        const uint32_t* Aw = Ah + (warp_m * 64) * ASTRW;
        const uint32_t* Alw = Al + (warp_m * 64) * ASTRW;
        #pragma unroll
        for (int ks = 0; ks < 2; ++ks) {
            const int kw = 8 * ks + tg;
            uint32_t ah[4][4], al[4][4];
            #pragma unroll
            for (int mt = 0; mt < 4; ++mt) {
                const int r0 = (mt * 16 + g) * ASTRW;
                const int r1 = (mt * 16 + g + 8) * ASTRW;
                ah[mt][0] = Aw[r0 + kw];      al[mt][0] = Alw[r0 + kw];
                ah[mt][1] = Aw[r1 + kw];      al[mt][1] = Alw[r1 + kw];
                ah[mt][2] = Aw[r0 + kw + 4];  al[mt][2] = Alw[r0 + kw + 4];
                ah[mt][3] = Aw[r1 + kw + 4];  al[mt][3] = Alw[r1 + kw + 4];
            }
            #pragma unroll
            for (int nt = 0; nt < 4; ++nt) {
                const int n = warp_n * 32 + nt * 8 + g;
                const int o0 = kw * BSTRW + n;
                const int o1 = (kw + 4) * BSTRW + n;
                uint32_t bh0 = Bh[o0], bh1 = Bh[o1];
                uint32_t bl0 = Bl[o0], bl1 = Bl[o1];
                #pragma unroll
                for (int mt = 0; mt < 4; ++mt) {
                    MMA_BF16(acc[mt][nt], al[mt][0], al[mt][1], al[mt][2], al[mt][3],
                             bh0, bh1);
                    MMA_BF16(acc[mt][nt], ah[mt][0], ah[mt][1], ah[mt][2], ah[mt][3],
                             bl0, bl1);
                    MMA_BF16(acc[mt][nt], ah[mt][0], ah[mt][1], ah[mt][2], ah[mt][3],
                             bh0, bh1);
                }
            }
        }
        __syncthreads();
        buf ^= 1;
    }

    float* Cb = C + (size_t)(bM + warp_m * 64) * N + bN + warp_n * 32;
    #pragma unroll
    for (int mt = 0; mt < 4; ++mt) {
        #pragma unroll
        for (int nt = 0; nt < 4; ++nt) {
            float* p0 = Cb + (size_t)(mt * 16 + g) * N + nt * 8 + 2 * tg;
            float* p1 = Cb + (size_t)(mt * 16 + g + 8) * N + nt * 8 + 2 * tg;
            *(float2*)p0 = make_float2(acc[mt][nt][0], acc[mt][nt][1]);
            *(float2*)p1 = make_float2(acc[mt][nt][2], acc[mt][nt][3]);
        }
    }
}

// ---------------------------------------------------------------------------
// bf16x3 tensor-core flash attention (m16n8k16) — unchanged (274us, 1.6e-5).
// ---------------------------------------------------------------------------
#define AQT  128
#define AKT  64
#define QSTRW 36
#define KSTRW 36
#define VSTRW 72

#define SM_QH   0
#define SM_QL   (SM_QH + 128 * QSTRW)
#define SM_KH   (SM_QL + 128 * QSTRW)
#define SM_KL   (SM_KH + 64 * KSTRW)
#define SM_VH   (SM_KL + 64 * KSTRW)
#define SM_VL   (SM_VH + 32 * VSTRW)
#define SM_MSK  (SM_VL + 32 * VSTRW)
#define ATTN_SMEM_BYTES ((SM_MSK + 64 + 16) * 4)   // 74,048 bytes

__global__ __launch_bounds__(256, 2)
void attn_mma(const float* __restrict__ Q, const float* __restrict__ K,
              const float* __restrict__ V, const int* __restrict__ mask,
              const int* __restrict__ causal_p, float* __restrict__ O)
{
    extern __shared__ uint32_t smw[];
    uint32_t* sQh = smw + SM_QH;
    uint32_t* sQl = smw + SM_QL;
    uint32_t* sKh = smw + SM_KH;
    uint32_t* sKl = smw + SM_KL;
    uint32_t* sVh = smw + SM_VH;
    uint32_t* sVl = smw + SM_VL;
    int*      sM  = (int*)(smw + SM_MSK);

    const int b   = blockIdx.z;
    const int h   = blockIdx.y;
    const int qt  = blockIdx.x;
    const int tid = threadIdx.x;
    const int lane = tid & 31;
    const int wid  = tid >> 5;
    const int g    = lane >> 2;
    const int tg   = lane & 3;
    const int m0   = wid * 16;
    const int causal = *causal_p;

    const float* Qg = Q + ((size_t)(b * SEQ + qt * AQT)) * DMODEL + h * HDIM;
    #pragma unroll
    for (int j = 0; j < 8; ++j) {
        int idx = tid + j * 256;
        int r = idx >> 4, cq = idx & 15;
        float4 qv = *(const float4*)(Qg + (size_t)r * DMODEL + cq * 4);
        uint32_t h0, l0, h1, l1;
        bf16x3_split(qv.x, qv.y, h0, l0);
        bf16x3_split(qv.z, qv.w, h1, l1);
        sQh[r * QSTRW + cq * 2]     = h0;
        sQh[r * QSTRW + cq * 2 + 1] = h1;
        sQl[r * QSTRW + cq * 2]     = l0;
        sQl[r * QSTRW + cq * 2 + 1] = l1;
    }

    float oacc[8][4];
    #pragma unroll
    for (int nt = 0; nt < 8; ++nt)
        #pragma unroll
        for (int c = 0; c < 4; ++c) oacc[nt][c] = 0.f;
    float mrun0 = -1e30f, mrun1 = -1e30f, l0s = 0.f, l1s = 0.f;

    const int ntiles = causal ? ((qt + 1) * (AQT / AKT)) : (SEQ / AKT);
    const float* Kg = K + ((size_t)(b * SEQ)) * DMODEL + h * HDIM;
    const float* Vg = V + ((size_t)(b * SEQ)) * DMODEL + h * HDIM;

    for (int t = 0; t < ntiles; ++t) {
        const int kbase = t * AKT;
        __syncthreads();

        #pragma unroll
        for (int j = 0; j < 4; ++j) {
            int idx = tid + j * 256;
            int r = idx >> 4, cq = idx & 15;
            float4 kv = *(const float4*)(Kg + (size_t)(kbase + r) * DMODEL + cq * 4);
            uint32_t h0, lo0, h1, lo1;
            bf16x3_split(kv.x, kv.y, h0, lo0);
            bf16x3_split(kv.z, kv.w, h1, lo1);
            sKh[r * KSTRW + cq * 2]     = h0;
            sKh[r * KSTRW + cq * 2 + 1] = h1;
            sKl[r * KSTRW + cq * 2]     = lo0;
            sKl[r * KSTRW + cq * 2 + 1] = lo1;
        }
        #pragma unroll
        for (int j = 0; j < 2; ++j) {
            int idx = tid + j * 256;
            int kp = idx >> 4, cq = idx & 15;
            const float* v0 = Vg + (size_t)(kbase + 2 * kp) * DMODEL + cq * 4;
            float4 a = *(const float4*)v0;
            float4 bb = *(const float4*)(v0 + DMODEL);
            uint32_t hh, ll;
            bf16x3_split(a.x, bb.x, hh, ll);
            sVh[kp * VSTRW + cq * 4 + 0] = hh; sVl[kp * VSTRW + cq * 4 + 0] = ll;
            bf16x3_split(a.y, bb.y, hh, ll);
            sVh[kp * VSTRW + cq * 4 + 1] = hh; sVl[kp * VSTRW + cq * 4 + 1] = ll;
            bf16x3_split(a.z, bb.z, hh, ll);
            sVh[kp * VSTRW + cq * 4 + 2] = hh; sVl[kp * VSTRW + cq * 4 + 2] = ll;
            bf16x3_split(a.w, bb.w, hh, ll);
            sVh[kp * VSTRW + cq * 4 + 3] = hh; sVl[kp * VSTRW + cq * 4 + 3] = ll;
        }
        if (tid < AKT) sM[tid] = mask[b * SEQ + kbase + tid];
        __syncthreads();

        float sacc[8][4];
        #pragma unroll
        for (int nt = 0; nt < 8; ++nt)
            #pragma unroll
            for (int c = 0; c < 4; ++c) sacc[nt][c] = 0.f;

        #pragma unroll
        for (int kt = 0; kt < 4; ++kt) {
            const int kw = 8 * kt + tg;
            uint32_t qh0 = sQh[(m0 + g) * QSTRW + kw];
            uint32_t qh1 = sQh[(m0 + g + 8) * QSTRW + kw];
            uint32_t qh2 = sQh[(m0 + g) * QSTRW + kw + 4];
            uint32_t qh3 = sQh[(m0 + g + 8) * QSTRW + kw + 4];
            uint32_t ql0 = sQl[(m0 + g) * QSTRW + kw];
            uint32_t ql1 = sQl[(m0 + g + 8) * QSTRW + kw];
            uint32_t ql2 = sQl[(m0 + g) * QSTRW + kw + 4];
            uint32_t ql3 = sQl[(m0 + g + 8) * QSTRW + kw + 4];
            #pragma unroll
            for (int nt = 0; nt < 8; ++nt) {
                const int ka = (nt * 8 + g) * KSTRW + kw;
                uint32_t bh0 = sKh[ka], bh1 = sKh[ka + 4];
                uint32_t bl0 = sKl[ka], bl1 = sKl[ka + 4];
                MMA_BF16(sacc[nt], ql0, ql1, ql2, ql3, bh0, bh1);
                MMA_BF16(sacc[nt], qh0, qh1, qh2, qh3, bl0, bl1);
                MMA_BF16(sacc[nt], qh0, qh1, qh2, qh3, bh0, bh1);
            }
        }

        const int row0 = qt * AQT + m0 + g;
        const int row1 = row0 + 8;
        const bool diag = causal && (kbase + AKT - 1 > qt * AQT + m0);
        float rmax0 = -1e30f, rmax1 = -1e30f;
        #pragma unroll
        for (int nt = 0; nt < 8; ++nt) {
            const int c0 = nt * 8 + 2 * tg;
            const int c1 = c0 + 1;
            const bool k0ok = sM[c0] != 0;
            const bool k1ok = sM[c1] != 0;
            const int gc0 = kbase + c0, gc1 = kbase + c1;
            bool v00 = k0ok && (!diag || gc0 <= row0);
            bool v01 = k1ok && (!diag || gc1 <= row0);
            bool v10 = k0ok && (!diag || gc0 <= row1);
            bool v11 = k1ok && (!diag || gc1 <= row1);
            sacc[nt][0] = v00 ? sacc[nt][0] * 0.125f : -1e30f;
            sacc[nt][1] = v01 ? sacc[nt][1] * 0.125f : -1e30f;
            sacc[nt][2] = v10 ? sacc[nt][2] * 0.125f : -1e30f;
            sacc[nt][3] = v11 ? sacc[nt][3] * 0.125f : -1e30f;
            rmax0 = fmaxf(rmax0, fmaxf(sacc[nt][0], sacc[nt][1]));
            rmax1 = fmaxf(rmax1, fmaxf(sacc[nt][2], sacc[nt][3]));
        }
        rmax0 = fmaxf(rmax0, __shfl_xor_sync(0xffffffffu, rmax0, 1));
        rmax0 = fmaxf(rmax0, __shfl_xor_sync(0xffffffffu, rmax0, 2));
        rmax1 = fmaxf(rmax1, __shfl_xor_sync(0xffffffffu, rmax1, 1));
        rmax1 = fmaxf(rmax1, __shfl_xor_sync(0xffffffffu, rmax1, 2));

        const float mnew0 = fmaxf(mrun0, rmax0);
        const float mnew1 = fmaxf(mrun1, rmax1);
        const float al0 = __expf(mrun0 - mnew0);
        const float al1 = __expf(mrun1 - mnew1);
        mrun0 = mnew0; mrun1 = mnew1;

        float rsum0 = 0.f, rsum1 = 0.f;
        #pragma unroll
        for (int nt = 0; nt < 8; ++nt) {
            sacc[nt][0] = __expf(sacc[nt][0] - mnew0);
            sacc[nt][1] = __expf(sacc[nt][1] - mnew0);
            sacc[nt][2] = __expf(sacc[nt][2] - mnew1);
            sacc[nt][3] = __expf(sacc[nt][3] - mnew1);
            rsum0 += sacc[nt][0] + sacc[nt][1];
            rsum1 += sacc[nt][2] + sacc[nt][3];
        }
        rsum0 += __shfl_xor_sync(0xffffffffu, rsum0, 1);
        rsum0 += __shfl_xor_sync(0xffffffffu, rsum0, 2);
        rsum1 += __shfl_xor_sync(0xffffffffu, rsum1, 1);
        rsum1 += __shfl_xor_sync(0xffffffffu, rsum1, 2);
        l0s = l0s * al0 + rsum0;
        l1s = l1s * al1 + rsum1;

        #pragma unroll
        for (int nt = 0; nt < 8; ++nt) {
            oacc[nt][0] *= al0; oacc[nt][1] *= al0;
            oacc[nt][2] *= al1; oacc[nt][3] *= al1;
        }

        #pragma unroll
        for (int kt = 0; kt < 4; ++kt) {
            uint32_t ph0, pl0, ph1, pl1, ph2, pl2, ph3, pl3;
            bf16x3_split(sacc[2 * kt][0],     sacc[2 * kt][1],     ph0, pl0);
            bf16x3_split(sacc[2 * kt][2],     sacc[2 * kt][3],     ph1, pl1);
            bf16x3_split(sacc[2 * kt + 1][0], sacc[2 * kt + 1][1], ph2, pl2);
            bf16x3_split(sacc[2 * kt + 1][2], sacc[2 * kt + 1][3], ph3, pl3);
            #pragma unroll
            for (int nt = 0; nt < 8; ++nt) {
                const int va = (8 * kt + tg) * VSTRW + nt * 8 + g;
                uint32_t bh0 = sVh[va], bh1 = sVh[va + 4 * VSTRW];
                uint32_t bl0 = sVl[va], bl1 = sVl[va + 4 * VSTRW];
                MMA_BF16(oacc[nt], pl0, pl1, pl2, pl3, bh0, bh1);
                MMA_BF16(oacc[nt], ph0, ph1, ph2, ph3, bl0, bl1);
                MMA_BF16(oacc[nt], ph0, ph1, ph2, ph3, bh0, bh1);
            }
        }
    }

    const float inv0 = 1.f / l0s;
    const float inv1 = 1.f / l1s;
    float* Og = O + ((size_t)(b * SEQ + qt * AQT + m0)) * DMODEL + h * HDIM;
    #pragma unroll
    for (int nt = 0; nt < 8; ++nt) {
        const int c = nt * 8 + 2 * tg;
        *(float2*)(Og + (size_t)g * DMODEL + c) =
            make_float2(oacc[nt][0] * inv0, oacc[nt][1] * inv0);
        *(float2*)(Og + (size_t)(g + 8) * DMODEL + c) =
            make_float2(oacc[nt][2] * inv1, oacc[nt][3] * inv1);
    }
}

// ---------------------------------------------------------------------------
// Launch
// ---------------------------------------------------------------------------
extern "C" void kernel_launch(void* const* d_in, const int* in_sizes, int n_in,
                              void* d_out, int out_size)
{
    const float* x      = (const float*)d_in[0];
    const int*   mask   = (const int*)  d_in[1];
    const int*   causal = (const int*)  d_in[2];
    const float* Wq     = (const float*)d_in[3];
    const float* Wk     = (const float*)d_in[4];
    const float* Wv     = (const float*)d_in[5];
    const float* Wo     = (const float*)d_in[6];
    float*       out    = (float*)d_out;

    float *qp, *kp, *vp, *ap;
    cudaGetSymbolAddress((void**)&qp, g_Q);
    cudaGetSymbolAddress((void**)&kp, g_K);
    cudaGetSymbolAddress((void**)&vp, g_V);
    cudaGetSymbolAddress((void**)&ap, g_A);

    static bool attr_done = false;
    if (!attr_done) {
        cudaFuncSetAttribute(bf16gemm, cudaFuncAttributeMaxDynamicSharedMemorySize,
                             GEMM_SMEM_BYTES);
        cudaFuncSetAttribute(attn_mma, cudaFuncAttributeMaxDynamicSharedMemorySize,
                             ATTN_SMEM_BYTES);
        attr_done = true;
    }

    dim3 ggrid(DMODEL / BN, MROWS / BM);   // (8, 32)
    dim3 gblk(256);

    bf16gemm<<<ggrid, gblk, GEMM_SMEM_BYTES>>>(x, Wq, qp, MROWS, DMODEL, DMODEL);
    bf16gemm<<<ggrid, gblk, GEMM_SMEM_BYTES>>>(x, Wk, kp, MROWS, DMODEL, DMODEL);
    bf16gemm<<<ggrid, gblk, GEMM_SMEM_BYTES>>>(x, Wv, vp, MROWS, DMODEL, DMODEL);

    dim3 agrid(SEQ / AQT, NHEAD, BATCH);   // (16, 16, 2)
    attn_mma<<<agrid, 256, ATTN_SMEM_BYTES>>>(qp, kp, vp, mask, causal, ap);

    bf16gemm<<<ggrid, gblk, GEMM_SMEM_BYTES>>>(ap, Wo, out, MROWS, DMODEL, DMODEL);
}